// round 2
// baseline (speedup 1.0000x reference)
#include <cuda_runtime.h>

#define DI __device__ __forceinline__
typedef unsigned long long ull;

constexpr int NT = 128;   // threads per block

// ---------------- packed f32x2 helpers (Blackwell) ----------------
DI ull pack2(float x, float y){
    ull v;
    asm("mov.b64 %0, {%1,%2};" : "=l"(v)
        : "r"(__float_as_uint(x)), "r"(__float_as_uint(y)));
    return v;
}
DI float2 unpack2(ull v){
    unsigned lo, hi;
    asm("mov.b64 {%0,%1}, %2;" : "=r"(lo), "=r"(hi) : "l"(v));
    return make_float2(__uint_as_float(lo), __uint_as_float(hi));
}
DI void ffma2(ull& d, ull a, ull b){
    asm("fma.rn.f32x2 %0, %1, %2, %0;" : "+l"(d) : "l"(a), "l"(b));
}
DI ull d2u(double d){ return __double_as_longlong(d); }

DI float gelu_exact(float x){
    return 0.5f * x * (1.0f + erff(x * 0.70710678118654752f));
}

// ---------------- shared memory layout (float offsets) ----------------
constexpr int OW1  = 0;            // 57*64 = 3648
constexpr int OW2  = 3648;         // 4096
constexpr int OW3  = 7744;         // 4096
constexpr int OW4  = 11840;        // 4096
constexpr int OW5  = 15936;        // 64*9 = 576
constexpr int OB1  = 16512;        // 64
constexpr int OB2  = 16576;        // 64
constexpr int OB3  = 16640;        // 64
constexpr int OB4  = 16704;        // 64
constexpr int OB5  = 16768;        // 16 (9 used)
constexpr int OLAT = 16784;        // 32
constexpr int OB1E = 16816;        // 64 (b1 + latent @ w1[25:57])
constexpr int OH   = 16880;        // 64*NT activations
constexpr int SMEM_FLOATS = OH + 64*NT;   // 25072 floats = 100288 B

// ---------------- dense layer: 64 outputs, packed-f32x2 MACs ----------------
// Activations stored column-per-thread: sh[k*NT + tid].
// Computes all 64 outputs in registers (32 ull accumulators), applies exact
// GELU, writes back into the SAME buffer (input fully consumed first).
template<int KD>
DI void dense_gelu(const float* __restrict__ sW,   // [KD][64] row-major
                   const float* __restrict__ sB,   // [64]
                   float* __restrict__ sh, int tid)
{
    ull acc[32];
    {
        const double2* bp = reinterpret_cast<const double2*>(sB);
        #pragma unroll
        for (int p = 0; p < 16; p++){
            double2 b = bp[p];
            acc[2*p]   = d2u(b.x);   // outputs (4p, 4p+1)
            acc[2*p+1] = d2u(b.y);   // outputs (4p+2, 4p+3)
        }
    }
    #pragma unroll 4
    for (int k = 0; k < KD; k++){
        float hk = sh[k*NT + tid];
        ull hh = pack2(hk, hk);
        const double2* wp = reinterpret_cast<const double2*>(sW + k*64);
        #pragma unroll
        for (int p = 0; p < 16; p++){
            double2 w = wp[p];
            ffma2(acc[2*p],   d2u(w.x), hh);
            ffma2(acc[2*p+1], d2u(w.y), hh);
        }
    }
    #pragma unroll
    for (int p = 0; p < 16; p++){
        float2 v0 = unpack2(acc[2*p]);
        float2 v1 = unpack2(acc[2*p+1]);
        int j = 4*p;
        sh[(j+0)*NT + tid] = gelu_exact(v0.x);
        sh[(j+1)*NT + tid] = gelu_exact(v0.y);
        sh[(j+2)*NT + tid] = gelu_exact(v1.x);
        sh[(j+3)*NT + tid] = gelu_exact(v1.y);
    }
}

// ---------------- main fused kernel ----------------
__global__ void __launch_bounds__(NT)
stress_fused_kernel(const float* __restrict__ Fg, const float* __restrict__ Cg,
                    const float* __restrict__ w1, const float* __restrict__ b1,
                    const float* __restrict__ w2, const float* __restrict__ b2,
                    const float* __restrict__ w3, const float* __restrict__ b3,
                    const float* __restrict__ w4, const float* __restrict__ b4,
                    const float* __restrict__ w5, const float* __restrict__ b5,
                    const float* __restrict__ tlw, const int* __restrict__ traj_ids,
                    float* __restrict__ outg, int B)
{
    extern __shared__ float sm[];
    const int tid = threadIdx.x;

    // ---- stage weights into shared memory ----
    for (int i = tid; i < 3648; i += NT) sm[OW1+i] = w1[i];
    for (int i = tid; i < 4096; i += NT){
        sm[OW2+i] = w2[i]; sm[OW3+i] = w3[i]; sm[OW4+i] = w4[i];
    }
    for (int i = tid; i < 576; i += NT) sm[OW5+i] = w5[i];
    if (tid < 64){
        sm[OB1+tid] = b1[tid]; sm[OB2+tid] = b2[tid];
        sm[OB3+tid] = b3[tid]; sm[OB4+tid] = b4[tid];
    }
    if (tid < 16) sm[OB5+tid] = (tid < 9) ? b5[tid] : 0.0f;
    if (tid < 32){
        int t = traj_ids[0];
        sm[OLAT+tid] = tlw[t*32 + tid];
    }
    __syncthreads();

    // ---- fold constant latent into layer-1 bias: b1e = b1 + lat @ w1[25:57] ----
    if (tid < 64){
        float a = sm[OB1+tid];
        #pragma unroll
        for (int e = 0; e < 32; e++)
            a = fmaf(sm[OLAT+e], sm[OW1 + (25+e)*64 + tid], a);
        sm[OB1E+tid] = a;
    }
    __syncthreads();

    float* sh = sm + OH;

    for (int base = blockIdx.x * NT; base < B; base += gridDim.x * NT){
        const int i = base + tid;

        // ---- load F ----
        float f[9];
        #pragma unroll
        for (int a = 0; a < 9; a++) f[a] = Fg[(size_t)i*9 + a];

        // ---- FtF (symmetric) ----
        float t00 = f[0]*f[0] + f[3]*f[3] + f[6]*f[6];
        float t01 = f[0]*f[1] + f[3]*f[4] + f[6]*f[7];
        float t02 = f[0]*f[2] + f[3]*f[5] + f[6]*f[8];
        float t11 = f[1]*f[1] + f[4]*f[4] + f[7]*f[7];
        float t12 = f[1]*f[2] + f[4]*f[5] + f[7]*f[8];
        float t22 = f[2]*f[2] + f[5]*f[5] + f[8]*f[8];

        // ---- det(F) ----
        float det = f[0]*(f[4]*f[8]-f[5]*f[7])
                  + f[1]*(f[5]*f[6]-f[3]*f[8])
                  + f[2]*(f[3]*f[7]-f[4]*f[6]);
        float dcl = (det < 0.0f) ? 1e-9f : det;

        // ---- singular values: trig eigenvalues of FtF, descending ----
        float q  = (t00 + t11 + t22) * (1.0f/3.0f);
        float p1 = t01*t01 + t02*t02 + t12*t12;
        float m0 = t00 - q, m1 = t11 - q, m2 = t22 - q;
        float p2 = m0*m0 + m1*m1 + m2*m2 + 2.0f*p1;
        float p  = sqrtf(p2 * (1.0f/6.0f) + 1e-30f);
        float ip = 1.0f / p;
        float b00 = m0*ip, b11 = m1*ip, b22 = m2*ip;
        float c01 = t01*ip, c02 = t02*ip, c12 = t12*ip;
        float detB = b00*(b11*b22 - c12*c12)
                   - c01*(c01*b22 - c12*c02)
                   + c02*(c01*c12 - b11*c02);
        float r = fminf(1.0f, fmaxf(-1.0f, 0.5f*detB));
        float phi = acosf(r) * (1.0f/3.0f);
        float e1 = q + 2.0f*p*cosf(phi);
        float e3 = q + 2.0f*p*cosf(phi + 2.0943951023931953f);
        float e2 = 3.0f*q - e1 - e3;
        float s1 = sqrtf(fmaxf(e1, 0.0f));
        float s2 = sqrtf(fmaxf(e2, 0.0f));
        float s3 = sqrtf(fmaxf(e3, 0.0f));

        // ---- polar rotation R = U @ Vh via Newton: X <- 0.5(X + X^-T) ----
        float R0=f[0],R1=f[1],R2=f[2],R3=f[3],R4=f[4],R5=f[5],R6=f[6],R7=f[7],R8=f[8];
        for (int it = 0; it < 8; it++){
            float C00 = R4*R8 - R5*R7;
            float C01 = R5*R6 - R3*R8;
            float C02 = R3*R7 - R4*R6;
            float C10 = R2*R7 - R1*R8;
            float C11 = R0*R8 - R2*R6;
            float C12 = R1*R6 - R0*R7;
            float C20 = R1*R5 - R2*R4;
            float C21 = R2*R3 - R0*R5;
            float C22 = R0*R4 - R1*R3;
            float dR  = R0*C00 + R1*C01 + R2*C02;
            float hd  = 0.5f / dR;
            R0 = 0.5f*R0 + C00*hd;  R1 = 0.5f*R1 + C01*hd;  R2 = 0.5f*R2 + C02*hd;
            R3 = 0.5f*R3 + C10*hd;  R4 = 0.5f*R4 + C11*hd;  R5 = 0.5f*R5 + C12*hd;
            R6 = 0.5f*R6 + C20*hd;  R7 = 0.5f*R7 + C21*hd;  R8 = 0.5f*R8 + C22*hd;
        }

        float F00c = fmaxf(f[0], 1e-6f);

        // ---- build h0 (25 features; latent already folded into bias) ----
        sh[ 0*NT+tid] = s1;  sh[ 1*NT+tid] = s2;  sh[ 2*NT+tid] = s3;
        sh[ 3*NT+tid] = t00; sh[ 4*NT+tid] = t01; sh[ 5*NT+tid] = t02;
        sh[ 6*NT+tid] = t01; sh[ 7*NT+tid] = t11; sh[ 8*NT+tid] = t12;
        sh[ 9*NT+tid] = t02; sh[10*NT+tid] = t12; sh[11*NT+tid] = t22;
        sh[12*NT+tid] = dcl;
        sh[13*NT+tid] = logf(dcl);
        sh[14*NT+tid] = F00c;
        sh[15*NT+tid] = logf(F00c);
        #pragma unroll
        for (int a = 0; a < 9; a++)
            sh[(16+a)*NT+tid] = Cg[(size_t)i*9 + a];

        // ---- MLP ----
        dense_gelu<25>(sm+OW1, sm+OB1E, sh, tid);
        dense_gelu<64>(sm+OW2, sm+OB2,  sh, tid);
        dense_gelu<64>(sm+OW3, sm+OB3,  sh, tid);
        dense_gelu<64>(sm+OW4, sm+OB4,  sh, tid);

        // ---- layer 5: 64 -> 9 ----
        float o[9];
        #pragma unroll
        for (int j = 0; j < 9; j++) o[j] = sm[OB5+j];
        #pragma unroll 4
        for (int k = 0; k < 64; k++){
            float hk = sh[k*NT + tid];
            #pragma unroll
            for (int j = 0; j < 9; j++)
                o[j] = fmaf(hk, sm[OW5 + k*9 + j], o[j]);
        }

        // ---- epilogue: sym, P = R*S, cauchy = P*F^T ----
        float s00 = o[0], s01 = 0.5f*(o[1]+o[3]), s02 = 0.5f*(o[2]+o[6]);
        float s11 = o[4], s12 = 0.5f*(o[5]+o[7]), s22 = o[8];

        float P00 = R0*s00 + R1*s01 + R2*s02;
        float P01 = R0*s01 + R1*s11 + R2*s12;
        float P02 = R0*s02 + R1*s12 + R2*s22;
        float P10 = R3*s00 + R4*s01 + R5*s02;
        float P11 = R3*s01 + R4*s11 + R5*s12;
        float P12 = R3*s02 + R4*s12 + R5*s22;
        float P20 = R6*s00 + R7*s01 + R8*s02;
        float P21 = R6*s01 + R7*s11 + R8*s12;
        float P22 = R6*s02 + R7*s12 + R8*s22;

        size_t o9 = (size_t)i*9;
        outg[o9+0] = P00*f[0] + P01*f[1] + P02*f[2];
        outg[o9+1] = P00*f[3] + P01*f[4] + P02*f[5];
        outg[o9+2] = P00*f[6] + P01*f[7] + P02*f[8];
        outg[o9+3] = P10*f[0] + P11*f[1] + P12*f[2];
        outg[o9+4] = P10*f[3] + P11*f[4] + P12*f[5];
        outg[o9+5] = P10*f[6] + P11*f[7] + P12*f[8];
        outg[o9+6] = P20*f[0] + P21*f[1] + P22*f[2];
        outg[o9+7] = P20*f[3] + P21*f[4] + P22*f[5];
        outg[o9+8] = P20*f[6] + P21*f[7] + P22*f[8];
    }
}

// ---------------- launch ----------------
extern "C" void kernel_launch(void* const* d_in, const int* in_sizes, int n_in,
                              void* d_out, int out_size)
{
    const float* F   = (const float*)d_in[0];
    const float* C   = (const float*)d_in[1];
    const float* w1  = (const float*)d_in[2];
    const float* b1  = (const float*)d_in[3];
    const float* w2  = (const float*)d_in[4];
    const float* b2  = (const float*)d_in[5];
    const float* w3  = (const float*)d_in[6];
    const float* b3  = (const float*)d_in[7];
    const float* w4  = (const float*)d_in[8];
    const float* b4  = (const float*)d_in[9];
    const float* w5  = (const float*)d_in[10];
    const float* b5  = (const float*)d_in[11];
    const float* tlw = (const float*)d_in[12];
    const int*   tid = (const int*)d_in[13];
    float* out = (float*)d_out;

    int B = in_sizes[0] / 9;
    int smem_bytes = SMEM_FLOATS * (int)sizeof(float);
    cudaFuncSetAttribute(stress_fused_kernel,
                         cudaFuncAttributeMaxDynamicSharedMemorySize, smem_bytes);

    int chunks = (B + NT - 1) / NT;
    int grid = chunks < 296 ? chunks : 296;   // 148 SMs x 2 blocks

    stress_fused_kernel<<<grid, NT, smem_bytes>>>(
        F, C, w1, b1, w2, b2, w3, b3, w4, b4, w5, b5, tlw, tid, out, B);
}

// round 4
// speedup vs baseline: 1.5046x; 1.5046x over previous
#include <cuda_runtime.h>
#include <cuda_fp16.h>
#include <cstdint>

#define DI __device__ __forceinline__

constexpr int NT = 128;   // 4 warps; warp w owns rows [32w, 32w+32)

// ---------------- smem layout (bytes) ----------------
// Weight fragments: per layer, [ntile][ktile][lane] -> uint2 {b0b1, b2b3}
constexpr int O_WF1H = 0;        // 8*2*32 uint2 = 4096 B
constexpr int O_WF1L = 4096;
constexpr int O_WF2H = 8192;     // 8*4*32 uint2 = 8192 B
constexpr int O_WF2L = 16384;
constexpr int O_WF3H = 24576;
constexpr int O_WF3L = 32768;
constexpr int O_WF4H = 40960;
constexpr int O_WF4L = 49152;
constexpr int O_WF5H = 57344;    // 2*4*32 uint2 = 2048 B
constexpr int O_WF5L = 59392;
constexpr int O_BIAS = 61440;    // 272 floats (b1e,b2,b3,b4,b5pad)
constexpr int O_FEATH = 62528;   // 128 rows * 40 halves * 2 B = 10240
constexpr int O_FEATL = 72768;   // 10240
constexpr int O_OUTS  = 83008;   // 128 rows * 20 floats * 4 B = 10240
constexpr int SMEM_BYTES = 93248;

// ---------------- helpers ----------------
DI float gelu_f(float x){
    // exact-GELU via branch-free A&S 7.1.26 erf (|err| <= 1.5e-7)
    float z  = 0.70710678118654752f * x;
    float az = fabsf(z);
    float t  = __fdividef(1.0f, fmaf(0.3275911f, az, 1.0f));
    float pl = t * fmaf(t, fmaf(t, fmaf(t, fmaf(t, 1.061405429f, -1.453152027f),
                         1.421413741f), -0.284496736f), 0.254829592f);
    float e  = __expf(-z * z);
    float ea = 1.0f - pl * e;
    return 0.5f * x * (1.0f + copysignf(ea, x));
}

DI void split2(float v0, float v1, unsigned &hi, unsigned &lo){
    half h0 = __float2half_rn(v0), h1 = __float2half_rn(v1);
    half l0 = __float2half_rn(v0 - __half2float(h0));
    half l1 = __float2half_rn(v1 - __half2float(h1));
    hi = ((unsigned)__half_as_ushort(h1) << 16) | (unsigned)__half_as_ushort(h0);
    lo = ((unsigned)__half_as_ushort(l1) << 16) | (unsigned)__half_as_ushort(l0);
}

DI void mma16816(float (&c)[4], const unsigned (&a)[4], uint2 b){
    asm volatile(
        "mma.sync.aligned.m16n8k16.row.col.f32.f16.f16.f32 "
        "{%0,%1,%2,%3}, {%4,%5,%6,%7}, {%8,%9}, {%0,%1,%2,%3};"
        : "+f"(c[0]), "+f"(c[1]), "+f"(c[2]), "+f"(c[3])
        : "r"(a[0]), "r"(a[1]), "r"(a[2]), "r"(a[3]), "r"(b.x), "r"(b.y));
}

// acc init from bias: c0,c1 = cols 8j+2t, 8j+2t+1 ; c2,c3 same cols (rows +8)
template<int NTI>
DI void init_acc(float (&acc)[2][8][4], const float* bias, int lane){
    int t2 = (lane & 3) * 2;
    #pragma unroll
    for (int j = 0; j < NTI; j++){
        float b0 = bias[j*8 + t2], b1 = bias[j*8 + t2 + 1];
        #pragma unroll
        for (int m = 0; m < 2; m++){
            acc[m][j][0] = b0; acc[m][j][1] = b1;
            acc[m][j][2] = b0; acc[m][j][3] = b1;
        }
    }
}

// one layer: hi/lo split => Ah*Bh + Ah*Bl + Al*Bh
template<int KT, int NTI>
DI void mma_block(float (&acc)[2][8][4],
                  const unsigned (&Ah)[2][4][4], const unsigned (&Al)[2][4][4],
                  const uint2* __restrict__ wfh, const uint2* __restrict__ wfl,
                  int lane){
    #pragma unroll
    for (int kt = 0; kt < KT; kt++){
        #pragma unroll
        for (int j = 0; j < NTI; j++){
            uint2 bh = wfh[(j*KT + kt)*32 + lane];
            uint2 bl = wfl[(j*KT + kt)*32 + lane];
            #pragma unroll
            for (int m = 0; m < 2; m++){
                mma16816(acc[m][j], Ah[m][kt], bh);
                mma16816(acc[m][j], Ah[m][kt], bl);
                mma16816(acc[m][j], Al[m][kt], bh);
            }
        }
    }
}

// D -> GELU -> next-layer A fragments (in registers).
// A reg r of ktile kk: r0=(ntile 2kk, c0c1) r1=(2kk, c2c3) r2=(2kk+1, c0c1) r3=(2kk+1, c2c3)
DI void act_frags(const float (&acc)[2][8][4],
                  unsigned (&Ah)[2][4][4], unsigned (&Al)[2][4][4]){
    #pragma unroll
    for (int m = 0; m < 2; m++)
    #pragma unroll
    for (int kk = 0; kk < 4; kk++)
    #pragma unroll
    for (int part = 0; part < 2; part++)
    #pragma unroll
    for (int pair = 0; pair < 2; pair++){
        int j = 2*kk + part;
        float v0 = gelu_f(acc[m][j][2*pair]);
        float v1 = gelu_f(acc[m][j][2*pair + 1]);
        split2(v0, v1, Ah[m][kk][part*2 + pair], Al[m][kk][part*2 + pair]);
    }
}

// layer-1 A fragments from feature smem (row-major, stride 40 halves)
template<int KT>
DI void load_feat_frags(const half* __restrict__ fbase, int row0, int lane,
                        unsigned (&A)[2][4][4]){
    int g = lane >> 2, t2 = (lane & 3) * 2;
    #pragma unroll
    for (int m = 0; m < 2; m++){
        int ra = row0 + m*16 + g;
        #pragma unroll
        for (int kt = 0; kt < KT; kt++){
            const half* p0 = fbase + ra*40 + kt*16 + t2;
            const half* p1 = fbase + (ra + 8)*40 + kt*16 + t2;
            A[m][kt][0] = *reinterpret_cast<const unsigned*>(p0);
            A[m][kt][1] = *reinterpret_cast<const unsigned*>(p1);
            A[m][kt][2] = *reinterpret_cast<const unsigned*>(p0 + 8);
            A[m][kt][3] = *reinterpret_cast<const unsigned*>(p1 + 8);
        }
    }
}

// stage weights into per-lane fragment order, fp16 hi/lo split
DI void stage(char* sm, int oh, int ol, const float* __restrict__ w,
              int Kreal, int Nreal, int ldw, int KT, int NTI, int tid){
    uint2* fh = reinterpret_cast<uint2*>(sm + oh);
    uint2* fl = reinterpret_cast<uint2*>(sm + ol);
    int total = NTI * KT * 32;
    for (int idx = tid; idx < total; idx += NT){
        int lane = idx & 31;
        int kt   = (idx >> 5) % KT;
        int nt   = idx / (32 * KT);
        int n  = nt*8 + (lane >> 2);
        int k0 = kt*16 + (lane & 3)*2;
        float v[4];
        #pragma unroll
        for (int q = 0; q < 4; q++){
            int k = k0 + (q >> 1)*8 + (q & 1);
            v[q] = (k < Kreal && n < Nreal) ? w[k*ldw + n] : 0.0f;
        }
        unsigned hx, lx, hy, ly;
        split2(v[0], v[1], hx, lx);
        split2(v[2], v[3], hy, ly);
        fh[idx] = make_uint2(hx, hy);
        fl[idx] = make_uint2(lx, ly);
    }
}

// ---------------- main fused kernel ----------------
__global__ void __launch_bounds__(NT)
stress_hmma_kernel(const float* __restrict__ Fg, const float* __restrict__ Cg,
                   const float* __restrict__ w1, const float* __restrict__ b1,
                   const float* __restrict__ w2, const float* __restrict__ b2,
                   const float* __restrict__ w3, const float* __restrict__ b3,
                   const float* __restrict__ w4, const float* __restrict__ b4,
                   const float* __restrict__ w5, const float* __restrict__ b5,
                   const float* __restrict__ tlw, const int* __restrict__ traj_ids,
                   float* __restrict__ outg, int B)
{
    extern __shared__ __align__(16) char sm[];
    const int tid  = threadIdx.x;
    const int lane = tid & 31;
    const int wbase = (tid >> 5) * 32;

    // ---- stage weight fragments (once) ----
    stage(sm, O_WF1H, O_WF1L, w1, 25, 64, 64, 2, 8, tid);
    stage(sm, O_WF2H, O_WF2L, w2, 64, 64, 64, 4, 8, tid);
    stage(sm, O_WF3H, O_WF3L, w3, 64, 64, 64, 4, 8, tid);
    stage(sm, O_WF4H, O_WF4L, w4, 64, 64, 64, 4, 8, tid);
    stage(sm, O_WF5H, O_WF5L, w5, 64,  9,  9, 4, 2, tid);

    // ---- biases; fold constant latent into b1 ----
    float* sb = reinterpret_cast<float*>(sm + O_BIAS);
    if (tid < 64){
        int t = traj_ids[0];
        float a = b1[tid];
        #pragma unroll
        for (int e = 0; e < 32; e++)
            a = fmaf(tlw[t*32 + e], w1[(25+e)*64 + tid], a);
        sb[tid]       = a;
        sb[64  + tid] = b2[tid];
        sb[128 + tid] = b3[tid];
        sb[192 + tid] = b4[tid];
    }
    if (tid < 16) sb[256 + tid] = (tid < 9) ? b5[tid] : 0.0f;
    __syncthreads();

    half*  fH   = reinterpret_cast<half*>(sm + O_FEATH);
    half*  fL   = reinterpret_cast<half*>(sm + O_FEATL);
    float* outS = reinterpret_cast<float*>(sm + O_OUTS);

    const uint2* WF1H = (const uint2*)(sm + O_WF1H);
    const uint2* WF1L = (const uint2*)(sm + O_WF1L);
    const uint2* WF2H = (const uint2*)(sm + O_WF2H);
    const uint2* WF2L = (const uint2*)(sm + O_WF2L);
    const uint2* WF3H = (const uint2*)(sm + O_WF3H);
    const uint2* WF3L = (const uint2*)(sm + O_WF3L);
    const uint2* WF4H = (const uint2*)(sm + O_WF4H);
    const uint2* WF4L = (const uint2*)(sm + O_WF4L);
    const uint2* WF5H = (const uint2*)(sm + O_WF5H);
    const uint2* WF5L = (const uint2*)(sm + O_WF5L);

    for (int base = blockIdx.x * NT; base < B; base += gridDim.x * NT){
        const int i  = base + tid;
        const bool ok = (i < B);

        // ---- load F (identity if OOB) ----
        float f[9];
        if (ok){
            #pragma unroll
            for (int a = 0; a < 9; a++) f[a] = Fg[(size_t)i*9 + a];
        } else {
            #pragma unroll
            for (int a = 0; a < 9; a++) f[a] = (a % 4 == 0) ? 1.0f : 0.0f;
        }

        // ---- FtF ----
        float t00 = f[0]*f[0] + f[3]*f[3] + f[6]*f[6];
        float t01 = f[0]*f[1] + f[3]*f[4] + f[6]*f[7];
        float t02 = f[0]*f[2] + f[3]*f[5] + f[6]*f[8];
        float t11 = f[1]*f[1] + f[4]*f[4] + f[7]*f[7];
        float t12 = f[1]*f[2] + f[4]*f[5] + f[7]*f[8];
        float t22 = f[2]*f[2] + f[5]*f[5] + f[8]*f[8];

        // ---- det(F) ----
        float det = f[0]*(f[4]*f[8]-f[5]*f[7])
                  + f[1]*(f[5]*f[6]-f[3]*f[8])
                  + f[2]*(f[3]*f[7]-f[4]*f[6]);
        float dcl = (det < 0.0f) ? 1e-9f : det;

        // ---- singular values (trig eigensolve of FtF, descending) ----
        float q  = (t00 + t11 + t22) * (1.0f/3.0f);
        float p1 = t01*t01 + t02*t02 + t12*t12;
        float m0 = t00 - q, m1 = t11 - q, m2 = t22 - q;
        float p2 = m0*m0 + m1*m1 + m2*m2 + 2.0f*p1;
        float p  = sqrtf(p2 * (1.0f/6.0f) + 1e-30f);
        float ip = 1.0f / p;
        float b00 = m0*ip, b11 = m1*ip, b22 = m2*ip;
        float c01 = t01*ip, c02 = t02*ip, c12 = t12*ip;
        float detB = b00*(b11*b22 - c12*c12)
                   - c01*(c01*b22 - c12*c02)
                   + c02*(c01*c12 - b11*c02);
        float r = fminf(1.0f, fmaxf(-1.0f, 0.5f*detB));
        float phi = acosf(r) * (1.0f/3.0f);
        float e1 = q + 2.0f*p*cosf(phi);
        float e3 = q + 2.0f*p*cosf(phi + 2.0943951023931953f);
        float e2 = 3.0f*q - e1 - e3;
        float s1 = sqrtf(fmaxf(e1, 0.0f));
        float s2 = sqrtf(fmaxf(e2, 0.0f));
        float s3 = sqrtf(fmaxf(e3, 0.0f));

        // ---- polar rotation: Newton X <- 0.5(X + X^-T) ----
        float R0=f[0],R1=f[1],R2=f[2],R3=f[3],R4=f[4],R5=f[5],R6=f[6],R7=f[7],R8=f[8];
        #pragma unroll 1
        for (int it = 0; it < 8; it++){
            float C00 = R4*R8 - R5*R7, C01 = R5*R6 - R3*R8, C02 = R3*R7 - R4*R6;
            float C10 = R2*R7 - R1*R8, C11 = R0*R8 - R2*R6, C12 = R1*R6 - R0*R7;
            float C20 = R1*R5 - R2*R4, C21 = R2*R3 - R0*R5, C22 = R0*R4 - R1*R3;
            float dR  = R0*C00 + R1*C01 + R2*C02;
            float hd  = 0.5f / dR;
            R0 = 0.5f*R0 + C00*hd; R1 = 0.5f*R1 + C01*hd; R2 = 0.5f*R2 + C02*hd;
            R3 = 0.5f*R3 + C10*hd; R4 = 0.5f*R4 + C11*hd; R5 = 0.5f*R5 + C12*hd;
            R6 = 0.5f*R6 + C20*hd; R7 = 0.5f*R7 + C21*hd; R8 = 0.5f*R8 + C22*hd;
        }

        float F00c = fmaxf(f[0], 1e-6f);

        // ---- features (25 real, pad to 32) -> smem hi/lo, row = tid ----
        {
            float ft[32];
            ft[0]=s1; ft[1]=s2; ft[2]=s3;
            ft[3]=t00; ft[4]=t01; ft[5]=t02;
            ft[6]=t01; ft[7]=t11; ft[8]=t12;
            ft[9]=t02; ft[10]=t12; ft[11]=t22;
            ft[12]=dcl; ft[13]=logf(dcl);
            ft[14]=F00c; ft[15]=logf(F00c);
            #pragma unroll
            for (int a = 0; a < 9; a++)
                ft[16+a] = ok ? Cg[(size_t)i*9 + a] : 0.0f;
            #pragma unroll
            for (int a = 25; a < 32; a++) ft[a] = 0.0f;

            unsigned* wh = reinterpret_cast<unsigned*>(fH + tid*40);
            unsigned* wl = reinterpret_cast<unsigned*>(fL + tid*40);
            #pragma unroll
            for (int c = 0; c < 16; c++){
                unsigned hv, lv;
                split2(ft[2*c], ft[2*c+1], hv, lv);
                wh[c] = hv; wl[c] = lv;
            }
        }
        __syncwarp();

        // ---- MLP on HMMA ----
        float acc[2][8][4];
        unsigned Ah[2][4][4], Al[2][4][4];

        load_feat_frags<2>(fH, wbase, lane, Ah);
        load_feat_frags<2>(fL, wbase, lane, Al);
        init_acc<8>(acc, sb, lane);
        mma_block<2,8>(acc, Ah, Al, WF1H, WF1L, lane);
        act_frags(acc, Ah, Al);

        init_acc<8>(acc, sb + 64, lane);
        mma_block<4,8>(acc, Ah, Al, WF2H, WF2L, lane);
        act_frags(acc, Ah, Al);

        init_acc<8>(acc, sb + 128, lane);
        mma_block<4,8>(acc, Ah, Al, WF3H, WF3L, lane);
        act_frags(acc, Ah, Al);

        init_acc<8>(acc, sb + 192, lane);
        mma_block<4,8>(acc, Ah, Al, WF4H, WF4L, lane);
        act_frags(acc, Ah, Al);

        init_acc<2>(acc, sb + 256, lane);
        mma_block<4,2>(acc, Ah, Al, WF5H, WF5L, lane);

        // ---- scatter layer-5 D to out smem (warp-local rows) ----
        {
            int g = lane >> 2, t2 = (lane & 3) * 2;
            #pragma unroll
            for (int m = 0; m < 2; m++){
                int row = wbase + m*16 + g;
                #pragma unroll
                for (int j = 0; j < 2; j++){
                    int col = j*8 + t2;
                    outS[row*20 + col]       = acc[m][j][0];
                    outS[row*20 + col + 1]   = acc[m][j][1];
                    outS[(row+8)*20 + col]   = acc[m][j][2];
                    outS[(row+8)*20 + col+1] = acc[m][j][3];
                }
            }
        }
        __syncwarp();

        float o[9];
        #pragma unroll
        for (int c = 0; c < 9; c++) o[c] = outS[tid*20 + c];

        // ---- epilogue: sym, P = R*S, cauchy = P*F^T ----
        float s00 = o[0], s01 = 0.5f*(o[1]+o[3]), s02 = 0.5f*(o[2]+o[6]);
        float s11 = o[4], s12 = 0.5f*(o[5]+o[7]), s22 = o[8];

        float P00 = R0*s00 + R1*s01 + R2*s02;
        float P01 = R0*s01 + R1*s11 + R2*s12;
        float P02 = R0*s02 + R1*s12 + R2*s22;
        float P10 = R3*s00 + R4*s01 + R5*s02;
        float P11 = R3*s01 + R4*s11 + R5*s12;
        float P12 = R3*s02 + R4*s12 + R5*s22;
        float P20 = R6*s00 + R7*s01 + R8*s02;
        float P21 = R6*s01 + R7*s11 + R8*s12;
        float P22 = R6*s02 + R7*s12 + R8*s22;

        if (ok){
            size_t o9 = (size_t)i*9;
            outg[o9+0] = P00*f[0] + P01*f[1] + P02*f[2];
            outg[o9+1] = P00*f[3] + P01*f[4] + P02*f[5];
            outg[o9+2] = P00*f[6] + P01*f[7] + P02*f[8];
            outg[o9+3] = P10*f[0] + P11*f[1] + P12*f[2];
            outg[o9+4] = P10*f[3] + P11*f[4] + P12*f[5];
            outg[o9+5] = P10*f[6] + P11*f[7] + P12*f[8];
            outg[o9+6] = P20*f[0] + P21*f[1] + P22*f[2];
            outg[o9+7] = P20*f[3] + P21*f[4] + P22*f[5];
            outg[o9+8] = P20*f[6] + P21*f[7] + P22*f[8];
        }
    }
}

// ---------------- launch ----------------
extern "C" void kernel_launch(void* const* d_in, const int* in_sizes, int n_in,
                              void* d_out, int out_size)
{
    const float* F   = (const float*)d_in[0];
    const float* C   = (const float*)d_in[1];
    const float* w1  = (const float*)d_in[2];
    const float* b1  = (const float*)d_in[3];
    const float* w2  = (const float*)d_in[4];
    const float* b2  = (const float*)d_in[5];
    const float* w3  = (const float*)d_in[6];
    const float* b3  = (const float*)d_in[7];
    const float* w4  = (const float*)d_in[8];
    const float* b4  = (const float*)d_in[9];
    const float* w5  = (const float*)d_in[10];
    const float* b5  = (const float*)d_in[11];
    const float* tlw = (const float*)d_in[12];
    const int*   tid = (const int*)d_in[13];
    float* out = (float*)d_out;

    int B = in_sizes[0] / 9;
    cudaFuncSetAttribute(stress_hmma_kernel,
                         cudaFuncAttributeMaxDynamicSharedMemorySize, SMEM_BYTES);

    int tiles = (B + NT - 1) / NT;
    int grid = tiles < 296 ? tiles : 296;   // 148 SMs x 2 CTAs

    stress_hmma_kernel<<<grid, NT, SMEM_BYTES>>>(
        F, C, w1, b1, w2, b2, w3, b3, w4, b4, w5, b5, tlw, tid, out, B);
}

// round 5
// speedup vs baseline: 2.2082x; 1.4676x over previous
#include <cuda_runtime.h>
#include <cuda_fp16.h>
#include <cstdint>

#define DI __device__ __forceinline__
typedef unsigned long long ull;

constexpr int NT = 128;   // 4 warps; warp w owns rows [32w, 32w+32)

// ---------------- smem layout (bytes) ----------------
// Weight fragments: per layer, [ntile][ktile][lane] -> uint2 {b0b1, b2b3}
constexpr int O_WF1H = 0;        // 8*2*32 uint2 = 4096 B
constexpr int O_WF1L = 4096;
constexpr int O_WF2H = 8192;     // 8*4*32 uint2 = 8192 B
constexpr int O_WF2L = 16384;
constexpr int O_WF3H = 24576;
constexpr int O_WF3L = 32768;
constexpr int O_WF4H = 40960;
constexpr int O_WF4L = 49152;
constexpr int O_WF5H = 57344;    // 2*4*32 uint2 = 2048 B
constexpr int O_WF5L = 59392;
constexpr int O_BIAS = 61440;    // 272 floats
constexpr int O_FEAT = 62528;    // 128 rows * 40 halves * 2 B = 10240 (feat hi, feat lo, outS time-multiplexed)
constexpr int SMEM_BYTES = 72768;

// ---------------- packed f32x2 helpers (validated in R2 on this harness) ----------------
DI ull pack2(float x, float y){
    ull v;
    asm("mov.b64 %0, {%1,%2};" : "=l"(v)
        : "r"(__float_as_uint(x)), "r"(__float_as_uint(y)));
    return v;
}
DI float2 unpack2(ull v){
    unsigned lo, hi;
    asm("mov.b64 {%0,%1}, %2;" : "=r"(lo), "=r"(hi) : "l"(v));
    return make_float2(__uint_as_float(lo), __uint_as_float(hi));
}
DI ull mul2(ull a, ull b){ ull d; asm("mul.rn.f32x2 %0,%1,%2;" : "=l"(d) : "l"(a), "l"(b)); return d; }
DI ull add2(ull a, ull b){ ull d; asm("add.rn.f32x2 %0,%1,%2;" : "=l"(d) : "l"(a), "l"(b)); return d; }
DI ull fma2(ull a, ull b, ull c){ ull d; asm("fma.rn.f32x2 %0,%1,%2,%3;" : "=l"(d) : "l"(a), "l"(b), "l"(c)); return d; }
DI float rcp_a(float x){ float r; asm("rcp.approx.f32 %0,%1;" : "=f"(r) : "f"(x)); return r; }
DI float ex2_a(float x){ float r; asm("ex2.approx.f32 %0,%1;" : "=f"(r) : "f"(x)); return r; }

DI ull dup2(float c){ unsigned u = __float_as_uint(c); return ((ull)u << 32) | u; }

// packed exact-GELU (A&S 7.1.26 erf, |err| <= 1.5e-7) on a column pair
DI ull gelu2(ull x){
    const ull C_Z   = dup2(0.70710678118654752f);
    const ull C_P   = dup2(0.3275911f);
    const ull C_ONE = dup2(1.0f);
    const ull C_A5  = dup2(1.061405429f);
    const ull C_A4  = dup2(-1.453152027f);
    const ull C_A3  = dup2(1.421413741f);
    const ull C_A2  = dup2(-0.284496736f);
    const ull C_A1  = dup2(0.254829592f);
    const ull C_NL2 = dup2(-1.4426950408889634f);
    const ull C_H   = dup2(0.5f);

    ull z  = mul2(x, C_Z);
    ull az = z & 0x7FFFFFFF7FFFFFFFull;
    ull w  = fma2(az, C_P, C_ONE);
    float2 wf = unpack2(w);
    ull t  = pack2(rcp_a(wf.x), rcp_a(wf.y));
    ull pl = fma2(t, C_A5, C_A4);
    pl = fma2(t, pl, C_A3);
    pl = fma2(t, pl, C_A2);
    pl = fma2(t, pl, C_A1);
    pl = mul2(pl, t);
    ull zm = mul2(z, C_NL2);
    ull m  = mul2(zm, z);
    float2 mf = unpack2(m);
    ull e  = pack2(ex2_a(mf.x), ex2_a(mf.y));
    ull pe = mul2(pl, e);
    ull ea = add2(C_ONE, pe ^ 0x8000000080000000ull);   // 1 - pl*e  (>= 0)
    ull er = ea | (z & 0x8000000080000000ull);          // copysign
    ull xh = mul2(x, C_H);
    return fma2(xh, er, xh);                            // 0.5x + 0.5x*erf
}

// split packed f32 pair -> f16x2 hi + f16x2 lo
DI void split_pair(ull g, unsigned &h2, unsigned &l2){
    float2 gf = unpack2(g);
    asm("cvt.rn.f16x2.f32 %0, %1, %2;" : "=r"(h2) : "f"(gf.y), "f"(gf.x));  // hi-half=y, lo-half=x
    float hx, hy;
    asm("{.reg .b16 lo,hi;\n mov.b32 {lo,hi}, %2;\n cvt.f32.f16 %0, lo;\n cvt.f32.f16 %1, hi;}\n"
        : "=f"(hx), "=f"(hy) : "r"(h2));
    float lx = gf.x - hx, ly = gf.y - hy;
    asm("cvt.rn.f16x2.f32 %0, %1, %2;" : "=r"(l2) : "f"(ly), "f"(lx));
}

DI void split2s(float v0, float v1, unsigned &hi, unsigned &lo){
    half h0 = __float2half_rn(v0), h1 = __float2half_rn(v1);
    half l0 = __float2half_rn(v0 - __half2float(h0));
    half l1 = __float2half_rn(v1 - __half2float(h1));
    hi = ((unsigned)__half_as_ushort(h1) << 16) | (unsigned)__half_as_ushort(h0);
    lo = ((unsigned)__half_as_ushort(l1) << 16) | (unsigned)__half_as_ushort(l0);
}

DI void mma16816(float (&c)[4], const unsigned (&a)[4], uint2 b){
    asm volatile(
        "mma.sync.aligned.m16n8k16.row.col.f32.f16.f16.f32 "
        "{%0,%1,%2,%3}, {%4,%5,%6,%7}, {%8,%9}, {%0,%1,%2,%3};"
        : "+f"(c[0]), "+f"(c[1]), "+f"(c[2]), "+f"(c[3])
        : "r"(a[0]), "r"(a[1]), "r"(a[2]), "r"(a[3]), "r"(b.x), "r"(b.y));
}

template<int NTI>
DI void init_acc(float (&acc)[2][8][4], const float* bias, int lane){
    int t2 = (lane & 3) * 2;
    #pragma unroll
    for (int j = 0; j < NTI; j++){
        float b0 = bias[j*8 + t2], b1 = bias[j*8 + t2 + 1];
        #pragma unroll
        for (int m = 0; m < 2; m++){
            acc[m][j][0] = b0; acc[m][j][1] = b1;
            acc[m][j][2] = b0; acc[m][j][3] = b1;
        }
    }
}

template<int KT, int NTI>
DI void mma_block(float (&acc)[2][8][4],
                  const unsigned (&Ah)[2][4][4], const unsigned (&Al)[2][4][4],
                  const uint2* __restrict__ wfh, const uint2* __restrict__ wfl,
                  int lane){
    #pragma unroll
    for (int kt = 0; kt < KT; kt++){
        #pragma unroll
        for (int j = 0; j < NTI; j++){
            uint2 bh = wfh[(j*KT + kt)*32 + lane];
            uint2 bl = wfl[(j*KT + kt)*32 + lane];
            #pragma unroll
            for (int m = 0; m < 2; m++){
                mma16816(acc[m][j], Ah[m][kt], bh);
                mma16816(acc[m][j], Ah[m][kt], bl);
                mma16816(acc[m][j], Al[m][kt], bh);
            }
        }
    }
}

// D -> packed GELU -> next-layer A fragments (registers only)
DI void act_frags(const float (&acc)[2][8][4],
                  unsigned (&Ah)[2][4][4], unsigned (&Al)[2][4][4]){
    #pragma unroll
    for (int m = 0; m < 2; m++)
    #pragma unroll
    for (int kk = 0; kk < 4; kk++)
    #pragma unroll
    for (int part = 0; part < 2; part++)
    #pragma unroll
    for (int pair = 0; pair < 2; pair++){
        int j = 2*kk + part;
        ull g = gelu2(pack2(acc[m][j][2*pair], acc[m][j][2*pair + 1]));
        split_pair(g, Ah[m][kk][part*2 + pair], Al[m][kk][part*2 + pair]);
    }
}

// layer-1 A fragments from feature smem (row-major, stride 40 halves)
template<int KT>
DI void load_feat_frags(const half* __restrict__ fbase, int row0, int lane,
                        unsigned (&A)[2][4][4]){
    int g = lane >> 2, t2 = (lane & 3) * 2;
    #pragma unroll
    for (int m = 0; m < 2; m++){
        int ra = row0 + m*16 + g;
        #pragma unroll
        for (int kt = 0; kt < KT; kt++){
            const half* p0 = fbase + ra*40 + kt*16 + t2;
            const half* p1 = fbase + (ra + 8)*40 + kt*16 + t2;
            A[m][kt][0] = *reinterpret_cast<const unsigned*>(p0);
            A[m][kt][1] = *reinterpret_cast<const unsigned*>(p1);
            A[m][kt][2] = *reinterpret_cast<const unsigned*>(p0 + 8);
            A[m][kt][3] = *reinterpret_cast<const unsigned*>(p1 + 8);
        }
    }
}

// stage weights into per-lane fragment order, fp16 hi/lo split
DI void stage(char* sm, int oh, int ol, const float* __restrict__ w,
              int Kreal, int Nreal, int ldw, int KT, int NTI, int tid){
    uint2* fh = reinterpret_cast<uint2*>(sm + oh);
    uint2* fl = reinterpret_cast<uint2*>(sm + ol);
    int total = NTI * KT * 32;
    for (int idx = tid; idx < total; idx += NT){
        int lane = idx & 31;
        int kt   = (idx >> 5) % KT;
        int nt   = idx / (32 * KT);
        int n  = nt*8 + (lane >> 2);
        int k0 = kt*16 + (lane & 3)*2;
        float v[4];
        #pragma unroll
        for (int q = 0; q < 4; q++){
            int k = k0 + (q >> 1)*8 + (q & 1);
            v[q] = (k < Kreal && n < Nreal) ? w[k*ldw + n] : 0.0f;
        }
        unsigned hx, lx, hy, ly;
        split2s(v[0], v[1], hx, lx);
        split2s(v[2], v[3], hy, ly);
        fh[idx] = make_uint2(hx, hy);
        fl[idx] = make_uint2(lx, ly);
    }
}

// ---------------- main fused kernel ----------------
__global__ void __launch_bounds__(NT, 3)
stress_hmma_kernel(const float* __restrict__ Fg, const float* __restrict__ Cg,
                   const float* __restrict__ w1, const float* __restrict__ b1,
                   const float* __restrict__ w2, const float* __restrict__ b2,
                   const float* __restrict__ w3, const float* __restrict__ b3,
                   const float* __restrict__ w4, const float* __restrict__ b4,
                   const float* __restrict__ w5, const float* __restrict__ b5,
                   const float* __restrict__ tlw, const int* __restrict__ traj_ids,
                   float* __restrict__ outg, int B)
{
    extern __shared__ __align__(16) char sm[];
    const int tid  = threadIdx.x;
    const int lane = tid & 31;
    const int wbase = (tid >> 5) * 32;

    // ---- stage weight fragments (once) ----
    stage(sm, O_WF1H, O_WF1L, w1, 25, 64, 64, 2, 8, tid);
    stage(sm, O_WF2H, O_WF2L, w2, 64, 64, 64, 4, 8, tid);
    stage(sm, O_WF3H, O_WF3L, w3, 64, 64, 64, 4, 8, tid);
    stage(sm, O_WF4H, O_WF4L, w4, 64, 64, 64, 4, 8, tid);
    stage(sm, O_WF5H, O_WF5L, w5, 64,  9,  9, 4, 2, tid);

    // ---- biases; fold constant latent into b1 ----
    float* sb = reinterpret_cast<float*>(sm + O_BIAS);
    if (tid < 64){
        int t = traj_ids[0];
        float a = b1[tid];
        #pragma unroll
        for (int e = 0; e < 32; e++)
            a = fmaf(tlw[t*32 + e], w1[(25+e)*64 + tid], a);
        sb[tid]       = a;
        sb[64  + tid] = b2[tid];
        sb[128 + tid] = b3[tid];
        sb[192 + tid] = b4[tid];
    }
    if (tid < 16) sb[256 + tid] = (tid < 9) ? b5[tid] : 0.0f;
    __syncthreads();

    half*  fB   = reinterpret_cast<half*>(sm + O_FEAT);   // warp-local, time-multiplexed
    float* outS = reinterpret_cast<float*>(sm + O_FEAT);  // alias (20 floats = 40 halves)

    const uint2* WF1H = (const uint2*)(sm + O_WF1H);
    const uint2* WF1L = (const uint2*)(sm + O_WF1L);
    const uint2* WF2H = (const uint2*)(sm + O_WF2H);
    const uint2* WF2L = (const uint2*)(sm + O_WF2L);
    const uint2* WF3H = (const uint2*)(sm + O_WF3H);
    const uint2* WF3L = (const uint2*)(sm + O_WF3L);
    const uint2* WF4H = (const uint2*)(sm + O_WF4H);
    const uint2* WF4L = (const uint2*)(sm + O_WF4L);
    const uint2* WF5H = (const uint2*)(sm + O_WF5H);
    const uint2* WF5L = (const uint2*)(sm + O_WF5L);

    for (int base = blockIdx.x * NT; base < B; base += gridDim.x * NT){
        const int i  = base + tid;
        const bool ok = (i < B);

        // ---- load F (identity if OOB) ----
        float f[9];
        if (ok){
            #pragma unroll
            for (int a = 0; a < 9; a++) f[a] = Fg[(size_t)i*9 + a];
        } else {
            #pragma unroll
            for (int a = 0; a < 9; a++) f[a] = (a % 4 == 0) ? 1.0f : 0.0f;
        }

        // ---- FtF ----
        float t00 = f[0]*f[0] + f[3]*f[3] + f[6]*f[6];
        float t01 = f[0]*f[1] + f[3]*f[4] + f[6]*f[7];
        float t02 = f[0]*f[2] + f[3]*f[5] + f[6]*f[8];
        float t11 = f[1]*f[1] + f[4]*f[4] + f[7]*f[7];
        float t12 = f[1]*f[2] + f[4]*f[5] + f[7]*f[8];
        float t22 = f[2]*f[2] + f[5]*f[5] + f[8]*f[8];

        // ---- det(F) ----
        float det = f[0]*(f[4]*f[8]-f[5]*f[7])
                  + f[1]*(f[5]*f[6]-f[3]*f[8])
                  + f[2]*(f[3]*f[7]-f[4]*f[6]);
        float dcl = (det < 0.0f) ? 1e-9f : det;

        // ---- singular values (trig eigensolve of FtF, descending) ----
        float q  = (t00 + t11 + t22) * (1.0f/3.0f);
        float p1 = t01*t01 + t02*t02 + t12*t12;
        float m0 = t00 - q, m1 = t11 - q, m2 = t22 - q;
        float p2 = m0*m0 + m1*m1 + m2*m2 + 2.0f*p1;
        float p  = sqrtf(p2 * (1.0f/6.0f) + 1e-30f);
        float ip = 1.0f / p;
        float b00 = m0*ip, b11 = m1*ip, b22 = m2*ip;
        float c01 = t01*ip, c02 = t02*ip, c12 = t12*ip;
        float detB = b00*(b11*b22 - c12*c12)
                   - c01*(c01*b22 - c12*c02)
                   + c02*(c01*c12 - b11*c02);
        float r = fminf(1.0f, fmaxf(-1.0f, 0.5f*detB));
        float phi = acosf(r) * (1.0f/3.0f);
        float e1 = q + 2.0f*p*cosf(phi);
        float e3 = q + 2.0f*p*cosf(phi + 2.0943951023931953f);
        float e2 = 3.0f*q - e1 - e3;
        float s1 = sqrtf(fmaxf(e1, 0.0f));
        float s2 = sqrtf(fmaxf(e2, 0.0f));
        float s3 = sqrtf(fmaxf(e3, 0.0f));

        // ---- polar rotation: Newton X <- 0.5(X + X^-T) ----
        float R0=f[0],R1=f[1],R2=f[2],R3=f[3],R4=f[4],R5=f[5],R6=f[6],R7=f[7],R8=f[8];
        #pragma unroll 1
        for (int it = 0; it < 8; it++){
            float C00 = R4*R8 - R5*R7, C01 = R5*R6 - R3*R8, C02 = R3*R7 - R4*R6;
            float C10 = R2*R7 - R1*R8, C11 = R0*R8 - R2*R6, C12 = R1*R6 - R0*R7;
            float C20 = R1*R5 - R2*R4, C21 = R2*R3 - R0*R5, C22 = R0*R4 - R1*R3;
            float dR  = R0*C00 + R1*C01 + R2*C02;
            float hd  = 0.5f / dR;
            R0 = 0.5f*R0 + C00*hd; R1 = 0.5f*R1 + C01*hd; R2 = 0.5f*R2 + C02*hd;
            R3 = 0.5f*R3 + C10*hd; R4 = 0.5f*R4 + C11*hd; R5 = 0.5f*R5 + C12*hd;
            R6 = 0.5f*R6 + C20*hd; R7 = 0.5f*R7 + C21*hd; R8 = 0.5f*R8 + C22*hd;
        }

        float F00c = fmaxf(f[0], 1e-6f);

        // ---- features (25 real, pad to 32): hi -> smem, keep lo in regs ----
        unsigned lv[16];
        {
            float ft[32];
            ft[0]=s1; ft[1]=s2; ft[2]=s3;
            ft[3]=t00; ft[4]=t01; ft[5]=t02;
            ft[6]=t01; ft[7]=t11; ft[8]=t12;
            ft[9]=t02; ft[10]=t12; ft[11]=t22;
            ft[12]=dcl; ft[13]=logf(dcl);
            ft[14]=F00c; ft[15]=logf(F00c);
            #pragma unroll
            for (int a = 0; a < 9; a++)
                ft[16+a] = ok ? Cg[(size_t)i*9 + a] : 0.0f;
            #pragma unroll
            for (int a = 25; a < 32; a++) ft[a] = 0.0f;

            unsigned* wrow = reinterpret_cast<unsigned*>(fB + tid*40);
            #pragma unroll
            for (int c = 0; c < 16; c++){
                unsigned hv, lw;
                split2s(ft[2*c], ft[2*c+1], hv, lw);
                wrow[c] = hv; lv[c] = lw;
            }
        }
        __syncwarp();

        float acc[2][8][4];
        unsigned Ah[2][4][4], Al[2][4][4];

        load_feat_frags<2>(fB, wbase, lane, Ah);
        __syncwarp();
        {   // overwrite with lo features
            unsigned* wrow = reinterpret_cast<unsigned*>(fB + tid*40);
            #pragma unroll
            for (int c = 0; c < 16; c++) wrow[c] = lv[c];
        }
        __syncwarp();
        load_feat_frags<2>(fB, wbase, lane, Al);

        // ---- MLP on HMMA ----
        init_acc<8>(acc, sb, lane);
        mma_block<2,8>(acc, Ah, Al, WF1H, WF1L, lane);
        act_frags(acc, Ah, Al);

        init_acc<8>(acc, sb + 64, lane);
        mma_block<4,8>(acc, Ah, Al, WF2H, WF2L, lane);
        act_frags(acc, Ah, Al);

        init_acc<8>(acc, sb + 128, lane);
        mma_block<4,8>(acc, Ah, Al, WF3H, WF3L, lane);
        act_frags(acc, Ah, Al);

        init_acc<8>(acc, sb + 192, lane);
        mma_block<4,8>(acc, Ah, Al, WF4H, WF4L, lane);
        act_frags(acc, Ah, Al);

        init_acc<2>(acc, sb + 256, lane);
        mma_block<4,2>(acc, Ah, Al, WF5H, WF5L, lane);

        // ---- scatter layer-5 D to warp-local out staging (aliases feature buf) ----
        __syncwarp();
        {
            int g = lane >> 2, t2 = (lane & 3) * 2;
            #pragma unroll
            for (int m = 0; m < 2; m++){
                int row = wbase + m*16 + g;
                #pragma unroll
                for (int j = 0; j < 2; j++){
                    int col = j*8 + t2;
                    outS[row*20 + col]       = acc[m][j][0];
                    outS[row*20 + col + 1]   = acc[m][j][1];
                    outS[(row+8)*20 + col]   = acc[m][j][2];
                    outS[(row+8)*20 + col+1] = acc[m][j][3];
                }
            }
        }
        __syncwarp();

        float o[9];
        #pragma unroll
        for (int c = 0; c < 9; c++) o[c] = outS[tid*20 + c];
        __syncwarp();

        // ---- epilogue: sym, P = R*S, cauchy = P*F^T ----
        float s00 = o[0], s01 = 0.5f*(o[1]+o[3]), s02 = 0.5f*(o[2]+o[6]);
        float s11 = o[4], s12 = 0.5f*(o[5]+o[7]), s22 = o[8];

        float P00 = R0*s00 + R1*s01 + R2*s02;
        float P01 = R0*s01 + R1*s11 + R2*s12;
        float P02 = R0*s02 + R1*s12 + R2*s22;
        float P10 = R3*s00 + R4*s01 + R5*s02;
        float P11 = R3*s01 + R4*s11 + R5*s12;
        float P12 = R3*s02 + R4*s12 + R5*s22;
        float P20 = R6*s00 + R7*s01 + R8*s02;
        float P21 = R6*s01 + R7*s11 + R8*s12;
        float P22 = R6*s02 + R7*s12 + R8*s22;

        if (ok){
            size_t o9 = (size_t)i*9;
            outg[o9+0] = P00*f[0] + P01*f[1] + P02*f[2];
            outg[o9+1] = P00*f[3] + P01*f[4] + P02*f[5];
            outg[o9+2] = P00*f[6] + P01*f[7] + P02*f[8];
            outg[o9+3] = P10*f[0] + P11*f[1] + P12*f[2];
            outg[o9+4] = P10*f[3] + P11*f[4] + P12*f[5];
            outg[o9+5] = P10*f[6] + P11*f[7] + P12*f[8];
            outg[o9+6] = P20*f[0] + P21*f[1] + P22*f[2];
            outg[o9+7] = P20*f[3] + P21*f[4] + P22*f[5];
            outg[o9+8] = P20*f[6] + P21*f[7] + P22*f[8];
        }
    }
}

// ---------------- launch ----------------
extern "C" void kernel_launch(void* const* d_in, const int* in_sizes, int n_in,
                              void* d_out, int out_size)
{
    const float* F   = (const float*)d_in[0];
    const float* C   = (const float*)d_in[1];
    const float* w1  = (const float*)d_in[2];
    const float* b1  = (const float*)d_in[3];
    const float* w2  = (const float*)d_in[4];
    const float* b2  = (const float*)d_in[5];
    const float* w3  = (const float*)d_in[6];
    const float* b3  = (const float*)d_in[7];
    const float* w4  = (const float*)d_in[8];
    const float* b4  = (const float*)d_in[9];
    const float* w5  = (const float*)d_in[10];
    const float* b5  = (const float*)d_in[11];
    const float* tlw = (const float*)d_in[12];
    const int*   tid = (const int*)d_in[13];
    float* out = (float*)d_out;

    int B = in_sizes[0] / 9;
    cudaFuncSetAttribute(stress_hmma_kernel,
                         cudaFuncAttributeMaxDynamicSharedMemorySize, SMEM_BYTES);

    int tiles = (B + NT - 1) / NT;
    int grid = tiles < 444 ? tiles : 444;   // 148 SMs x 3 CTAs

    stress_hmma_kernel<<<grid, NT, SMEM_BYTES>>>(
        F, C, w1, b1, w2, b2, w3, b3, w4, b4, w5, b5, tlw, tid, out, B);
}

// round 6
// speedup vs baseline: 2.8695x; 1.2995x over previous
#include <cuda_runtime.h>
#include <cuda_fp16.h>
#include <cstdint>

#define DI __device__ __forceinline__
typedef unsigned long long ull;

constexpr int NT   = 256;  // 8 warps; warp w owns m-tile rows [16w, 16w+16)
constexpr int TILE = 128;  // items per CTA-tile

// ---------------- smem layout (bytes) ----------------
constexpr int O_WF1H = 0;        // 8*2*32 uint2 = 4096 B
constexpr int O_WF1L = 4096;
constexpr int O_WF2H = 8192;     // 8*4*32 uint2 = 8192 B
constexpr int O_WF2L = 16384;
constexpr int O_WF3H = 24576;
constexpr int O_WF3L = 32768;
constexpr int O_WF4H = 40960;
constexpr int O_WF4L = 49152;
constexpr int O_WF5H = 57344;    // 2*4*32 uint2 = 2048 B
constexpr int O_WF5L = 59392;
constexpr int O_BIAS = 61440;    // 272 floats
constexpr int O_FEAT = 62528;    // 128 rows * 40 halves * 2B = 10240 (feat-hi / feat-lo / outS multiplexed)
constexpr int SMEM_BYTES = 72768;

// ---------------- packed f32x2 helpers ----------------
DI ull pack2(float x, float y){
    ull v;
    asm("mov.b64 %0, {%1,%2};" : "=l"(v)
        : "r"(__float_as_uint(x)), "r"(__float_as_uint(y)));
    return v;
}
DI float2 unpack2(ull v){
    unsigned lo, hi;
    asm("mov.b64 {%0,%1}, %2;" : "=r"(lo), "=r"(hi) : "l"(v));
    return make_float2(__uint_as_float(lo), __uint_as_float(hi));
}
DI ull mul2(ull a, ull b){ ull d; asm("mul.rn.f32x2 %0,%1,%2;" : "=l"(d) : "l"(a), "l"(b)); return d; }
DI ull add2(ull a, ull b){ ull d; asm("add.rn.f32x2 %0,%1,%2;" : "=l"(d) : "l"(a), "l"(b)); return d; }
DI ull fma2(ull a, ull b, ull c){ ull d; asm("fma.rn.f32x2 %0,%1,%2,%3;" : "=l"(d) : "l"(a), "l"(b), "l"(c)); return d; }
DI float rcp_a(float x){ float r; asm("rcp.approx.f32 %0,%1;" : "=f"(r) : "f"(x)); return r; }
DI float ex2_a(float x){ float r; asm("ex2.approx.f32 %0,%1;" : "=f"(r) : "f"(x)); return r; }
DI ull dup2(float c){ unsigned u = __float_as_uint(c); return ((ull)u << 32) | u; }

// packed exact-GELU (A&S 7.1.26 erf, |err| <= 1.5e-7) on a column pair
DI ull gelu2(ull x){
    const ull C_Z   = dup2(0.70710678118654752f);
    const ull C_P   = dup2(0.3275911f);
    const ull C_ONE = dup2(1.0f);
    const ull C_A5  = dup2(1.061405429f);
    const ull C_A4  = dup2(-1.453152027f);
    const ull C_A3  = dup2(1.421413741f);
    const ull C_A2  = dup2(-0.284496736f);
    const ull C_A1  = dup2(0.254829592f);
    const ull C_NL2 = dup2(-1.4426950408889634f);
    const ull C_H   = dup2(0.5f);

    ull z  = mul2(x, C_Z);
    ull az = z & 0x7FFFFFFF7FFFFFFFull;
    ull w  = fma2(az, C_P, C_ONE);
    float2 wf = unpack2(w);
    ull t  = pack2(rcp_a(wf.x), rcp_a(wf.y));
    ull pl = fma2(t, C_A5, C_A4);
    pl = fma2(t, pl, C_A3);
    pl = fma2(t, pl, C_A2);
    pl = fma2(t, pl, C_A1);
    pl = mul2(pl, t);
    ull zm = mul2(z, C_NL2);
    ull m  = mul2(zm, z);
    float2 mf = unpack2(m);
    ull e  = pack2(ex2_a(mf.x), ex2_a(mf.y));
    ull pe = mul2(pl, e);
    ull ea = add2(C_ONE, pe ^ 0x8000000080000000ull);   // 1 - pl*e
    ull er = ea | (z & 0x8000000080000000ull);          // copysign
    ull xh = mul2(x, C_H);
    return fma2(xh, er, xh);                            // 0.5x + 0.5x*erf
}

// split packed f32 pair -> f16x2 hi + f16x2 lo
DI void split_pair(ull g, unsigned &h2, unsigned &l2){
    float2 gf = unpack2(g);
    asm("cvt.rn.f16x2.f32 %0, %1, %2;" : "=r"(h2) : "f"(gf.y), "f"(gf.x));
    float hx, hy;
    asm("{.reg .b16 lo,hi;\n mov.b32 {lo,hi}, %2;\n cvt.f32.f16 %0, lo;\n cvt.f32.f16 %1, hi;}\n"
        : "=f"(hx), "=f"(hy) : "r"(h2));
    float lx = gf.x - hx, ly = gf.y - hy;
    asm("cvt.rn.f16x2.f32 %0, %1, %2;" : "=r"(l2) : "f"(ly), "f"(lx));
}

DI void split2s(float v0, float v1, unsigned &hi, unsigned &lo){
    half h0 = __float2half_rn(v0), h1 = __float2half_rn(v1);
    half l0 = __float2half_rn(v0 - __half2float(h0));
    half l1 = __float2half_rn(v1 - __half2float(h1));
    hi = ((unsigned)__half_as_ushort(h1) << 16) | (unsigned)__half_as_ushort(h0);
    lo = ((unsigned)__half_as_ushort(l1) << 16) | (unsigned)__half_as_ushort(l0);
}

DI void mma16816(float (&c)[4], const unsigned (&a)[4], uint2 b){
    asm volatile(
        "mma.sync.aligned.m16n8k16.row.col.f32.f16.f16.f32 "
        "{%0,%1,%2,%3}, {%4,%5,%6,%7}, {%8,%9}, {%0,%1,%2,%3};"
        : "+f"(c[0]), "+f"(c[1]), "+f"(c[2]), "+f"(c[3])
        : "r"(a[0]), "r"(a[1]), "r"(a[2]), "r"(a[3]), "r"(b.x), "r"(b.y));
}

template<int NTI>
DI void init_acc1(float (&acc)[8][4], const float* bias, int lane){
    int t2 = (lane & 3) * 2;
    #pragma unroll
    for (int j = 0; j < NTI; j++){
        float b0 = bias[j*8 + t2], b1 = bias[j*8 + t2 + 1];
        acc[j][0] = b0; acc[j][1] = b1;
        acc[j][2] = b0; acc[j][3] = b1;
    }
}

// one layer (single m-tile): Ah*Bh + Ah*Bl + Al*Bh
template<int KT, int NTI>
DI void mma_block1(float (&acc)[8][4],
                   const unsigned (&Ah)[4][4], const unsigned (&Al)[4][4],
                   const uint2* __restrict__ wfh, const uint2* __restrict__ wfl,
                   int lane){
    #pragma unroll
    for (int kt = 0; kt < KT; kt++){
        #pragma unroll
        for (int j = 0; j < NTI; j++){
            uint2 bh = wfh[(j*KT + kt)*32 + lane];
            uint2 bl = wfl[(j*KT + kt)*32 + lane];
            mma16816(acc[j], Ah[kt], bh);
            mma16816(acc[j], Ah[kt], bl);
            mma16816(acc[j], Al[kt], bh);
        }
    }
}

// D -> packed GELU -> next-layer A fragments (registers only)
DI void act_frags1(const float (&acc)[8][4],
                   unsigned (&Ah)[4][4], unsigned (&Al)[4][4]){
    #pragma unroll
    for (int kk = 0; kk < 4; kk++)
    #pragma unroll
    for (int part = 0; part < 2; part++)
    #pragma unroll
    for (int pair = 0; pair < 2; pair++){
        int j = 2*kk + part;
        ull g = gelu2(pack2(acc[j][2*pair], acc[j][2*pair + 1]));
        split_pair(g, Ah[kk][part*2 + pair], Al[kk][part*2 + pair]);
    }
}

// A fragments for one 16-row m-tile from feature smem (row stride 40 halves)
template<int KT>
DI void load_feat_frags1(const half* __restrict__ fbase, int row0, int lane,
                         unsigned (&A)[4][4]){
    int g = lane >> 2, t2 = (lane & 3) * 2;
    int ra = row0 + g;
    #pragma unroll
    for (int kt = 0; kt < KT; kt++){
        const half* p0 = fbase + ra*40 + kt*16 + t2;
        const half* p1 = fbase + (ra + 8)*40 + kt*16 + t2;
        A[kt][0] = *reinterpret_cast<const unsigned*>(p0);
        A[kt][1] = *reinterpret_cast<const unsigned*>(p1);
        A[kt][2] = *reinterpret_cast<const unsigned*>(p0 + 8);
        A[kt][3] = *reinterpret_cast<const unsigned*>(p1 + 8);
    }
}

// stage weights into per-lane fragment order, fp16 hi/lo split
DI void stage(char* sm, int oh, int ol, const float* __restrict__ w,
              int Kreal, int Nreal, int ldw, int KT, int NTI, int tid){
    uint2* fh = reinterpret_cast<uint2*>(sm + oh);
    uint2* fl = reinterpret_cast<uint2*>(sm + ol);
    int total = NTI * KT * 32;
    for (int idx = tid; idx < total; idx += NT){
        int lane = idx & 31;
        int kt   = (idx >> 5) % KT;
        int nt   = idx / (32 * KT);
        int n  = nt*8 + (lane >> 2);
        int k0 = kt*16 + (lane & 3)*2;
        float v[4];
        #pragma unroll
        for (int q = 0; q < 4; q++){
            int k = k0 + (q >> 1)*8 + (q & 1);
            v[q] = (k < Kreal && n < Nreal) ? w[k*ldw + n] : 0.0f;
        }
        unsigned hx, lx, hy, ly;
        split2s(v[0], v[1], hx, lx);
        split2s(v[2], v[3], hy, ly);
        fh[idx] = make_uint2(hx, hy);
        fl[idx] = make_uint2(lx, ly);
    }
}

// ---------------- main fused kernel ----------------
__global__ void __launch_bounds__(NT, 2)
stress_hmma_kernel(const float* __restrict__ Fg, const float* __restrict__ Cg,
                   const float* __restrict__ w1, const float* __restrict__ b1,
                   const float* __restrict__ w2, const float* __restrict__ b2,
                   const float* __restrict__ w3, const float* __restrict__ b3,
                   const float* __restrict__ w4, const float* __restrict__ b4,
                   const float* __restrict__ w5, const float* __restrict__ b5,
                   const float* __restrict__ tlw, const int* __restrict__ traj_ids,
                   float* __restrict__ outg, int B)
{
    extern __shared__ __align__(16) char sm[];
    const int tid   = threadIdx.x;
    const int lane  = tid & 31;
    const int mrow0 = (tid >> 5) * 16;      // warp's m-tile base row (8 warps x 16 rows)

    // ---- stage weight fragments (once) ----
    stage(sm, O_WF1H, O_WF1L, w1, 25, 64, 64, 2, 8, tid);
    stage(sm, O_WF2H, O_WF2L, w2, 64, 64, 64, 4, 8, tid);
    stage(sm, O_WF3H, O_WF3L, w3, 64, 64, 64, 4, 8, tid);
    stage(sm, O_WF4H, O_WF4L, w4, 64, 64, 64, 4, 8, tid);
    stage(sm, O_WF5H, O_WF5L, w5, 64,  9,  9, 4, 2, tid);

    // ---- biases; fold constant latent into b1 ----
    float* sb = reinterpret_cast<float*>(sm + O_BIAS);
    if (tid < 64){
        int t = traj_ids[0];
        float a = b1[tid];
        #pragma unroll
        for (int e = 0; e < 32; e++)
            a = fmaf(tlw[t*32 + e], w1[(25+e)*64 + tid], a);
        sb[tid]       = a;
        sb[64  + tid] = b2[tid];
        sb[128 + tid] = b3[tid];
        sb[192 + tid] = b4[tid];
    }
    if (tid < 16) sb[256 + tid] = (tid < 9) ? b5[tid] : 0.0f;
    __syncthreads();

    half*  fB   = reinterpret_cast<half*>(sm + O_FEAT);   // 128 rows x 40 halves (time-multiplexed)
    float* outS = reinterpret_cast<float*>(sm + O_FEAT);  // alias: 128 rows x 20 floats

    const uint2* WF1H = (const uint2*)(sm + O_WF1H);
    const uint2* WF1L = (const uint2*)(sm + O_WF1L);
    const uint2* WF2H = (const uint2*)(sm + O_WF2H);
    const uint2* WF2L = (const uint2*)(sm + O_WF2L);
    const uint2* WF3H = (const uint2*)(sm + O_WF3H);
    const uint2* WF3L = (const uint2*)(sm + O_WF3L);
    const uint2* WF4H = (const uint2*)(sm + O_WF4H);
    const uint2* WF4L = (const uint2*)(sm + O_WF4L);
    const uint2* WF5H = (const uint2*)(sm + O_WF5H);
    const uint2* WF5L = (const uint2*)(sm + O_WF5L);

    for (int base = blockIdx.x * TILE; base < B; base += gridDim.x * TILE){
        const int  i    = base + tid;          // valid only for tid < TILE
        const bool mine = (tid < TILE);
        const bool ok   = mine && (i < B);

        float f[9];
        float R0=1,R1=0,R2=0,R3=0,R4=1,R5=0,R6=0,R7=0,R8=1;
        unsigned lv[16];

        if (mine){
            // ---- load F (identity if OOB) ----
            if (ok){
                #pragma unroll
                for (int a = 0; a < 9; a++) f[a] = Fg[(size_t)i*9 + a];
            } else {
                #pragma unroll
                for (int a = 0; a < 9; a++) f[a] = (a % 4 == 0) ? 1.0f : 0.0f;
            }

            // ---- FtF ----
            float t00 = f[0]*f[0] + f[3]*f[3] + f[6]*f[6];
            float t01 = f[0]*f[1] + f[3]*f[4] + f[6]*f[7];
            float t02 = f[0]*f[2] + f[3]*f[5] + f[6]*f[8];
            float t11 = f[1]*f[1] + f[4]*f[4] + f[7]*f[7];
            float t12 = f[1]*f[2] + f[4]*f[5] + f[7]*f[8];
            float t22 = f[2]*f[2] + f[5]*f[5] + f[8]*f[8];

            // ---- det(F) ----
            float det = f[0]*(f[4]*f[8]-f[5]*f[7])
                      + f[1]*(f[5]*f[6]-f[3]*f[8])
                      + f[2]*(f[3]*f[7]-f[4]*f[6]);
            float dcl = (det < 0.0f) ? 1e-9f : det;

            // ---- singular values (trig eigensolve of FtF, descending) ----
            float q  = (t00 + t11 + t22) * (1.0f/3.0f);
            float p1 = t01*t01 + t02*t02 + t12*t12;
            float m0 = t00 - q, m1 = t11 - q, m2 = t22 - q;
            float p2 = m0*m0 + m1*m1 + m2*m2 + 2.0f*p1;
            float p  = sqrtf(p2 * (1.0f/6.0f) + 1e-30f);
            float ip = 1.0f / p;
            float b00 = m0*ip, b11 = m1*ip, b22 = m2*ip;
            float c01 = t01*ip, c02 = t02*ip, c12 = t12*ip;
            float detB = b00*(b11*b22 - c12*c12)
                       - c01*(c01*b22 - c12*c02)
                       + c02*(c01*c12 - b11*c02);
            float r = fminf(1.0f, fmaxf(-1.0f, 0.5f*detB));
            float phi = acosf(r) * (1.0f/3.0f);
            float e1 = q + 2.0f*p*cosf(phi);
            float e3 = q + 2.0f*p*cosf(phi + 2.0943951023931953f);
            float e2 = 3.0f*q - e1 - e3;
            float s1 = sqrtf(fmaxf(e1, 0.0f));
            float s2 = sqrtf(fmaxf(e2, 0.0f));
            float s3 = sqrtf(fmaxf(e3, 0.0f));

            // ---- polar rotation: Newton X <- 0.5(X + X^-T) ----
            R0=f[0];R1=f[1];R2=f[2];R3=f[3];R4=f[4];R5=f[5];R6=f[6];R7=f[7];R8=f[8];
            #pragma unroll 1
            for (int it = 0; it < 8; it++){
                float C00 = R4*R8 - R5*R7, C01 = R5*R6 - R3*R8, C02 = R3*R7 - R4*R6;
                float C10 = R2*R7 - R1*R8, C11 = R0*R8 - R2*R6, C12 = R1*R6 - R0*R7;
                float C20 = R1*R5 - R2*R4, C21 = R2*R3 - R0*R5, C22 = R0*R4 - R1*R3;
                float dR  = R0*C00 + R1*C01 + R2*C02;
                float hd  = 0.5f / dR;
                R0 = 0.5f*R0 + C00*hd; R1 = 0.5f*R1 + C01*hd; R2 = 0.5f*R2 + C02*hd;
                R3 = 0.5f*R3 + C10*hd; R4 = 0.5f*R4 + C11*hd; R5 = 0.5f*R5 + C12*hd;
                R6 = 0.5f*R6 + C20*hd; R7 = 0.5f*R7 + C21*hd; R8 = 0.5f*R8 + C22*hd;
            }

            float F00c = fmaxf(f[0], 1e-6f);

            // ---- features (25 real, pad to 32): hi -> smem, lo kept in regs ----
            float ft[32];
            ft[0]=s1; ft[1]=s2; ft[2]=s3;
            ft[3]=t00; ft[4]=t01; ft[5]=t02;
            ft[6]=t01; ft[7]=t11; ft[8]=t12;
            ft[9]=t02; ft[10]=t12; ft[11]=t22;
            ft[12]=dcl; ft[13]=logf(dcl);
            ft[14]=F00c; ft[15]=logf(F00c);
            #pragma unroll
            for (int a = 0; a < 9; a++)
                ft[16+a] = ok ? Cg[(size_t)i*9 + a] : 0.0f;
            #pragma unroll
            for (int a = 25; a < 32; a++) ft[a] = 0.0f;

            unsigned* wrow = reinterpret_cast<unsigned*>(fB + tid*40);
            #pragma unroll
            for (int c = 0; c < 16; c++){
                unsigned hv, lw;
                split2s(ft[2*c], ft[2*c+1], hv, lw);
                wrow[c] = hv; lv[c] = lw;
            }
        }
        __syncthreads();                       // S1: feat-hi visible

        float acc[8][4];
        unsigned Ah[4][4], Al[4][4];

        load_feat_frags1<2>(fB, mrow0, lane, Ah);
        __syncthreads();                       // S2: all Ah reads done
        if (mine){
            unsigned* wrow = reinterpret_cast<unsigned*>(fB + tid*40);
            #pragma unroll
            for (int c = 0; c < 16; c++) wrow[c] = lv[c];
        }
        __syncthreads();                       // S3: feat-lo visible
        load_feat_frags1<2>(fB, mrow0, lane, Al);

        // ---- MLP on HMMA ----
        init_acc1<8>(acc, sb, lane);
        mma_block1<2,8>(acc, Ah, Al, WF1H, WF1L, lane);
        act_frags1(acc, Ah, Al);

        init_acc1<8>(acc, sb + 64, lane);
        mma_block1<4,8>(acc, Ah, Al, WF2H, WF2L, lane);
        act_frags1(acc, Ah, Al);

        init_acc1<8>(acc, sb + 128, lane);
        mma_block1<4,8>(acc, Ah, Al, WF3H, WF3L, lane);
        act_frags1(acc, Ah, Al);

        init_acc1<8>(acc, sb + 192, lane);
        mma_block1<4,8>(acc, Ah, Al, WF4H, WF4L, lane);
        act_frags1(acc, Ah, Al);

        init_acc1<2>(acc, sb + 256, lane);
        mma_block1<4,2>(acc, Ah, Al, WF5H, WF5L, lane);

        // ---- scatter layer-5 D to staging (rows of own m-tile; aliases fB) ----
        {
            int g = lane >> 2, t2 = (lane & 3) * 2;
            int row = mrow0 + g;
            #pragma unroll
            for (int j = 0; j < 2; j++){
                int col = j*8 + t2;
                outS[row*20 + col]       = acc[j][0];
                outS[row*20 + col + 1]   = acc[j][1];
                outS[(row+8)*20 + col]   = acc[j][2];
                outS[(row+8)*20 + col+1] = acc[j][3];
            }
        }
        __syncthreads();                       // S4: outS visible

        if (ok){
            float o[9];
            #pragma unroll
            for (int c = 0; c < 9; c++) o[c] = outS[tid*20 + c];

            // ---- epilogue: sym, P = R*S, cauchy = P*F^T ----
            float s00 = o[0], s01 = 0.5f*(o[1]+o[3]), s02 = 0.5f*(o[2]+o[6]);
            float s11 = o[4], s12 = 0.5f*(o[5]+o[7]), s22 = o[8];

            float P00 = R0*s00 + R1*s01 + R2*s02;
            float P01 = R0*s01 + R1*s11 + R2*s12;
            float P02 = R0*s02 + R1*s12 + R2*s22;
            float P10 = R3*s00 + R4*s01 + R5*s02;
            float P11 = R3*s01 + R4*s11 + R5*s12;
            float P12 = R3*s02 + R4*s12 + R5*s22;
            float P20 = R6*s00 + R7*s01 + R8*s02;
            float P21 = R6*s01 + R7*s11 + R8*s12;
            float P22 = R6*s02 + R7*s12 + R8*s22;

            size_t o9 = (size_t)i*9;
            outg[o9+0] = P00*f[0] + P01*f[1] + P02*f[2];
            outg[o9+1] = P00*f[3] + P01*f[4] + P02*f[5];
            outg[o9+2] = P00*f[6] + P01*f[7] + P02*f[8];
            outg[o9+3] = P10*f[0] + P11*f[1] + P12*f[2];
            outg[o9+4] = P10*f[3] + P11*f[4] + P12*f[5];
            outg[o9+5] = P10*f[6] + P11*f[7] + P12*f[8];
            outg[o9+6] = P20*f[0] + P21*f[1] + P22*f[2];
            outg[o9+7] = P20*f[3] + P21*f[4] + P22*f[5];
            outg[o9+8] = P20*f[6] + P21*f[7] + P22*f[8];
        }
    }
}

// ---------------- launch ----------------
extern "C" void kernel_launch(void* const* d_in, const int* in_sizes, int n_in,
                              void* d_out, int out_size)
{
    const float* F   = (const float*)d_in[0];
    const float* C   = (const float*)d_in[1];
    const float* w1  = (const float*)d_in[2];
    const float* b1  = (const float*)d_in[3];
    const float* w2  = (const float*)d_in[4];
    const float* b2  = (const float*)d_in[5];
    const float* w3  = (const float*)d_in[6];
    const float* b3  = (const float*)d_in[7];
    const float* w4  = (const float*)d_in[8];
    const float* b4  = (const float*)d_in[9];
    const float* w5  = (const float*)d_in[10];
    const float* b5  = (const float*)d_in[11];
    const float* tlw = (const float*)d_in[12];
    const int*   tid = (const int*)d_in[13];
    float* out = (float*)d_out;

    int B = in_sizes[0] / 9;
    cudaFuncSetAttribute(stress_hmma_kernel,
                         cudaFuncAttributeMaxDynamicSharedMemorySize, SMEM_BYTES);

    int tiles = (B + TILE - 1) / TILE;
    int grid = tiles < 296 ? tiles : 296;   // 148 SMs x 2 CTAs

    stress_hmma_kernel<<<grid, NT, SMEM_BYTES>>>(
        F, C, w1, b1, w2, b2, w3, b3, w4, b4, w5, b5, tlw, tid, out, B);
}

// round 7
// speedup vs baseline: 3.5944x; 1.2526x over previous
#include <cuda_runtime.h>
#include <cuda_fp16.h>
#include <cstdint>

#define DI __device__ __forceinline__
typedef unsigned long long ull;

constexpr int NT   = 256;  // 8 warps; warp w owns m-tile rows [16w, 16w+16)
constexpr int TILE = 128;  // items per CTA-tile

// ---------------- smem layout (bytes) ----------------
constexpr int O_WF1H = 0;        // 8*2*32 uint2 = 4096 B
constexpr int O_WF1L = 4096;
constexpr int O_WF2H = 8192;     // 8*4*32 uint2 = 8192 B
constexpr int O_WF2L = 16384;
constexpr int O_WF3H = 24576;
constexpr int O_WF3L = 32768;
constexpr int O_WF4H = 40960;
constexpr int O_WF4L = 49152;
constexpr int O_WF5H = 57344;    // 2*4*32 uint2 = 2048 B
constexpr int O_WF5L = 59392;
constexpr int O_BIAS = 61440;    // 272 floats
constexpr int O_FEAT = 62528;    // 128 rows * 40 halves * 2B = 10240 (feat-hi / outS multiplexed)
constexpr int SMEM_BYTES = 72768;

// ---------------- packed f32x2 helpers ----------------
DI ull pack2(float x, float y){
    ull v;
    asm("mov.b64 %0, {%1,%2};" : "=l"(v)
        : "r"(__float_as_uint(x)), "r"(__float_as_uint(y)));
    return v;
}
DI float2 unpack2(ull v){
    unsigned lo, hi;
    asm("mov.b64 {%0,%1}, %2;" : "=r"(lo), "=r"(hi) : "l"(v));
    return make_float2(__uint_as_float(lo), __uint_as_float(hi));
}
DI ull mul2(ull a, ull b){ ull d; asm("mul.rn.f32x2 %0,%1,%2;" : "=l"(d) : "l"(a), "l"(b)); return d; }
DI ull add2(ull a, ull b){ ull d; asm("add.rn.f32x2 %0,%1,%2;" : "=l"(d) : "l"(a), "l"(b)); return d; }
DI ull fma2(ull a, ull b, ull c){ ull d; asm("fma.rn.f32x2 %0,%1,%2,%3;" : "=l"(d) : "l"(a), "l"(b), "l"(c)); return d; }
DI float rcp_a(float x){ float r; asm("rcp.approx.f32 %0,%1;" : "=f"(r) : "f"(x)); return r; }
DI float ex2_a(float x){ float r; asm("ex2.approx.f32 %0,%1;" : "=f"(r) : "f"(x)); return r; }
DI ull dup2(float c){ unsigned u = __float_as_uint(c); return ((ull)u << 32) | u; }

// packed exact-GELU (A&S 7.1.26 erf, |err| <= 1.5e-7) on a column pair
DI ull gelu2(ull x){
    const ull C_Z   = dup2(0.70710678118654752f);
    const ull C_P   = dup2(0.3275911f);
    const ull C_ONE = dup2(1.0f);
    const ull C_A5  = dup2(1.061405429f);
    const ull C_A4  = dup2(-1.453152027f);
    const ull C_A3  = dup2(1.421413741f);
    const ull C_A2  = dup2(-0.284496736f);
    const ull C_A1  = dup2(0.254829592f);
    const ull C_NL2 = dup2(-1.4426950408889634f);
    const ull C_H   = dup2(0.5f);

    ull z  = mul2(x, C_Z);
    ull az = z & 0x7FFFFFFF7FFFFFFFull;
    ull w  = fma2(az, C_P, C_ONE);
    float2 wf = unpack2(w);
    ull t  = pack2(rcp_a(wf.x), rcp_a(wf.y));
    ull pl = fma2(t, C_A5, C_A4);
    pl = fma2(t, pl, C_A3);
    pl = fma2(t, pl, C_A2);
    pl = fma2(t, pl, C_A1);
    pl = mul2(pl, t);
    ull zm = mul2(z, C_NL2);
    ull m  = mul2(zm, z);
    float2 mf = unpack2(m);
    ull e  = pack2(ex2_a(mf.x), ex2_a(mf.y));
    ull pe = mul2(pl, e);
    ull ea = add2(C_ONE, pe ^ 0x8000000080000000ull);   // 1 - pl*e
    ull er = ea | (z & 0x8000000080000000ull);          // copysign
    ull xh = mul2(x, C_H);
    return fma2(xh, er, xh);                            // 0.5x + 0.5x*erf
}

// packed f32 pair -> f16x2 (hi only; activation-lo term dropped by design)
DI unsigned cvt_h2(ull g){
    float2 gf = unpack2(g);
    unsigned h2;
    asm("cvt.rn.f16x2.f32 %0, %1, %2;" : "=r"(h2) : "f"(gf.y), "f"(gf.x));
    return h2;
}

DI void split2s(float v0, float v1, unsigned &hi, unsigned &lo){
    half h0 = __float2half_rn(v0), h1 = __float2half_rn(v1);
    half l0 = __float2half_rn(v0 - __half2float(h0));
    half l1 = __float2half_rn(v1 - __half2float(h1));
    hi = ((unsigned)__half_as_ushort(h1) << 16) | (unsigned)__half_as_ushort(h0);
    lo = ((unsigned)__half_as_ushort(l1) << 16) | (unsigned)__half_as_ushort(l0);
}

DI void mma16816(float (&c)[4], const unsigned (&a)[4], uint2 b){
    asm volatile(
        "mma.sync.aligned.m16n8k16.row.col.f32.f16.f16.f32 "
        "{%0,%1,%2,%3}, {%4,%5,%6,%7}, {%8,%9}, {%0,%1,%2,%3};"
        : "+f"(c[0]), "+f"(c[1]), "+f"(c[2]), "+f"(c[3])
        : "r"(a[0]), "r"(a[1]), "r"(a[2]), "r"(a[3]), "r"(b.x), "r"(b.y));
}

template<int NTI>
DI void init_acc1(float (&acc)[8][4], const float* bias, int lane){
    int t2 = (lane & 3) * 2;
    #pragma unroll
    for (int j = 0; j < NTI; j++){
        float2 b2v = *reinterpret_cast<const float2*>(bias + j*8 + t2);
        acc[j][0] = b2v.x; acc[j][1] = b2v.y;
        acc[j][2] = b2v.x; acc[j][3] = b2v.y;
    }
}

// one layer (single m-tile): Ah*Bh + Ah*Bl  (weight hi/lo, activation hi only)
template<int KT, int NTI>
DI void mma_block1(float (&acc)[8][4],
                   const unsigned (&Ah)[4][4],
                   const uint2* __restrict__ wfh, const uint2* __restrict__ wfl,
                   int lane){
    #pragma unroll
    for (int kt = 0; kt < KT; kt++){
        #pragma unroll
        for (int j = 0; j < NTI; j++){
            uint2 bh = wfh[(j*KT + kt)*32 + lane];
            uint2 bl = wfl[(j*KT + kt)*32 + lane];
            mma16816(acc[j], Ah[kt], bh);
            mma16816(acc[j], Ah[kt], bl);
        }
    }
}

// D -> packed GELU -> next-layer A fragments (registers only, hi precision)
DI void act_frags1(const float (&acc)[8][4], unsigned (&Ah)[4][4]){
    #pragma unroll
    for (int kk = 0; kk < 4; kk++)
    #pragma unroll
    for (int part = 0; part < 2; part++)
    #pragma unroll
    for (int pair = 0; pair < 2; pair++){
        int j = 2*kk + part;
        ull g = gelu2(pack2(acc[j][2*pair], acc[j][2*pair + 1]));
        Ah[kk][part*2 + pair] = cvt_h2(g);
    }
}

// A fragments for one 16-row m-tile from feature smem (row stride 40 halves)
template<int KT>
DI void load_feat_frags1(const half* __restrict__ fbase, int row0, int lane,
                         unsigned (&A)[4][4]){
    int g = lane >> 2, t2 = (lane & 3) * 2;
    int ra = row0 + g;
    #pragma unroll
    for (int kt = 0; kt < KT; kt++){
        const half* p0 = fbase + ra*40 + kt*16 + t2;
        const half* p1 = fbase + (ra + 8)*40 + kt*16 + t2;
        A[kt][0] = *reinterpret_cast<const unsigned*>(p0);
        A[kt][1] = *reinterpret_cast<const unsigned*>(p1);
        A[kt][2] = *reinterpret_cast<const unsigned*>(p0 + 8);
        A[kt][3] = *reinterpret_cast<const unsigned*>(p1 + 8);
    }
}

// stage weights into per-lane fragment order, fp16 hi/lo split
DI void stage(char* sm, int oh, int ol, const float* __restrict__ w,
              int Kreal, int Nreal, int ldw, int KT, int NTI, int tid){
    uint2* fh = reinterpret_cast<uint2*>(sm + oh);
    uint2* fl = reinterpret_cast<uint2*>(sm + ol);
    int total = NTI * KT * 32;
    for (int idx = tid; idx < total; idx += NT){
        int lane = idx & 31;
        int kt   = (idx >> 5) % KT;
        int nt   = idx / (32 * KT);
        int n  = nt*8 + (lane >> 2);
        int k0 = kt*16 + (lane & 3)*2;
        float v[4];
        #pragma unroll
        for (int q = 0; q < 4; q++){
            int k = k0 + (q >> 1)*8 + (q & 1);
            v[q] = (k < Kreal && n < Nreal) ? w[k*ldw + n] : 0.0f;
        }
        unsigned hx, lx, hy, ly;
        split2s(v[0], v[1], hx, lx);
        split2s(v[2], v[3], hy, ly);
        fh[idx] = make_uint2(hx, hy);
        fl[idx] = make_uint2(lx, ly);
    }
}

// ---------------- main fused kernel ----------------
__global__ void __launch_bounds__(NT, 2)
stress_hmma_kernel(const float* __restrict__ Fg, const float* __restrict__ Cg,
                   const float* __restrict__ w1, const float* __restrict__ b1,
                   const float* __restrict__ w2, const float* __restrict__ b2,
                   const float* __restrict__ w3, const float* __restrict__ b3,
                   const float* __restrict__ w4, const float* __restrict__ b4,
                   const float* __restrict__ w5, const float* __restrict__ b5,
                   const float* __restrict__ tlw, const int* __restrict__ traj_ids,
                   float* __restrict__ outg, int B)
{
    extern __shared__ __align__(16) char sm[];
    const int tid   = threadIdx.x;
    const int lane  = tid & 31;
    const int mrow0 = (tid >> 5) * 16;      // warp's m-tile base row (8 warps x 16 rows)

    // ---- stage weight fragments (once) ----
    stage(sm, O_WF1H, O_WF1L, w1, 25, 64, 64, 2, 8, tid);
    stage(sm, O_WF2H, O_WF2L, w2, 64, 64, 64, 4, 8, tid);
    stage(sm, O_WF3H, O_WF3L, w3, 64, 64, 64, 4, 8, tid);
    stage(sm, O_WF4H, O_WF4L, w4, 64, 64, 64, 4, 8, tid);
    stage(sm, O_WF5H, O_WF5L, w5, 64,  9,  9, 4, 2, tid);

    // ---- biases; fold constant latent into b1 ----
    float* sb = reinterpret_cast<float*>(sm + O_BIAS);
    if (tid < 64){
        int t = traj_ids[0];
        float a = b1[tid];
        #pragma unroll
        for (int e = 0; e < 32; e++)
            a = fmaf(tlw[t*32 + e], w1[(25+e)*64 + tid], a);
        sb[tid]       = a;
        sb[64  + tid] = b2[tid];
        sb[128 + tid] = b3[tid];
        sb[192 + tid] = b4[tid];
    }
    if (tid < 16) sb[256 + tid] = (tid < 9) ? b5[tid] : 0.0f;
    __syncthreads();

    half*  fB   = reinterpret_cast<half*>(sm + O_FEAT);   // 128 rows x 40 halves (time-multiplexed)
    float* outS = reinterpret_cast<float*>(sm + O_FEAT);  // alias: 128 rows x 20 floats

    const uint2* WF1H = (const uint2*)(sm + O_WF1H);
    const uint2* WF1L = (const uint2*)(sm + O_WF1L);
    const uint2* WF2H = (const uint2*)(sm + O_WF2H);
    const uint2* WF2L = (const uint2*)(sm + O_WF2L);
    const uint2* WF3H = (const uint2*)(sm + O_WF3H);
    const uint2* WF3L = (const uint2*)(sm + O_WF3L);
    const uint2* WF4H = (const uint2*)(sm + O_WF4H);
    const uint2* WF4L = (const uint2*)(sm + O_WF4L);
    const uint2* WF5H = (const uint2*)(sm + O_WF5H);
    const uint2* WF5L = (const uint2*)(sm + O_WF5L);

    for (int base = blockIdx.x * TILE; base < B; base += gridDim.x * TILE){
        const int  i    = base + tid;          // valid only for tid < TILE
        const bool mine = (tid < TILE);
        const bool ok   = mine && (i < B);

        float f[9];
        float R0=1,R1=0,R2=0,R3=0,R4=1,R5=0,R6=0,R7=0,R8=1;

        if (mine){
            // ---- load F (identity if OOB) ----
            if (ok){
                #pragma unroll
                for (int a = 0; a < 9; a++) f[a] = Fg[(size_t)i*9 + a];
            } else {
                #pragma unroll
                for (int a = 0; a < 9; a++) f[a] = (a % 4 == 0) ? 1.0f : 0.0f;
            }

            // ---- FtF ----
            float t00 = f[0]*f[0] + f[3]*f[3] + f[6]*f[6];
            float t01 = f[0]*f[1] + f[3]*f[4] + f[6]*f[7];
            float t02 = f[0]*f[2] + f[3]*f[5] + f[6]*f[8];
            float t11 = f[1]*f[1] + f[4]*f[4] + f[7]*f[7];
            float t12 = f[1]*f[2] + f[4]*f[5] + f[7]*f[8];
            float t22 = f[2]*f[2] + f[5]*f[5] + f[8]*f[8];

            // ---- det(F) ----
            float det = f[0]*(f[4]*f[8]-f[5]*f[7])
                      + f[1]*(f[5]*f[6]-f[3]*f[8])
                      + f[2]*(f[3]*f[7]-f[4]*f[6]);
            float dcl = (det < 0.0f) ? 1e-9f : det;

            // ---- singular values (trig eigensolve of FtF, descending) ----
            float q  = (t00 + t11 + t22) * (1.0f/3.0f);
            float p1 = t01*t01 + t02*t02 + t12*t12;
            float m0 = t00 - q, m1 = t11 - q, m2 = t22 - q;
            float p2 = m0*m0 + m1*m1 + m2*m2 + 2.0f*p1;
            float p  = sqrtf(p2 * (1.0f/6.0f) + 1e-30f);
            float ip = 1.0f / p;
            float b00 = m0*ip, b11 = m1*ip, b22 = m2*ip;
            float c01 = t01*ip, c02 = t02*ip, c12 = t12*ip;
            float detB = b00*(b11*b22 - c12*c12)
                       - c01*(c01*b22 - c12*c02)
                       + c02*(c01*c12 - b11*c02);
            float r = fminf(1.0f, fmaxf(-1.0f, 0.5f*detB));
            float phi = acosf(r) * (1.0f/3.0f);
            float e1 = q + 2.0f*p*cosf(phi);
            float e3 = q + 2.0f*p*cosf(phi + 2.0943951023931953f);
            float e2 = 3.0f*q - e1 - e3;
            float s1 = sqrtf(fmaxf(e1, 0.0f));
            float s2 = sqrtf(fmaxf(e2, 0.0f));
            float s3 = sqrtf(fmaxf(e3, 0.0f));

            // ---- polar rotation: Newton X <- 0.5(X + X^-T) ----
            R0=f[0];R1=f[1];R2=f[2];R3=f[3];R4=f[4];R5=f[5];R6=f[6];R7=f[7];R8=f[8];
            #pragma unroll 1
            for (int it = 0; it < 8; it++){
                float C00 = R4*R8 - R5*R7, C01 = R5*R6 - R3*R8, C02 = R3*R7 - R4*R6;
                float C10 = R2*R7 - R1*R8, C11 = R0*R8 - R2*R6, C12 = R1*R6 - R0*R7;
                float C20 = R1*R5 - R2*R4, C21 = R2*R3 - R0*R5, C22 = R0*R4 - R1*R3;
                float dR  = R0*C00 + R1*C01 + R2*C02;
                float hd  = 0.5f / dR;
                R0 = 0.5f*R0 + C00*hd; R1 = 0.5f*R1 + C01*hd; R2 = 0.5f*R2 + C02*hd;
                R3 = 0.5f*R3 + C10*hd; R4 = 0.5f*R4 + C11*hd; R5 = 0.5f*R5 + C12*hd;
                R6 = 0.5f*R6 + C20*hd; R7 = 0.5f*R7 + C21*hd; R8 = 0.5f*R8 + C22*hd;
            }

            float F00c = fmaxf(f[0], 1e-6f);

            // ---- features (25 real, pad to 32): fp16 -> smem ----
            float ft[32];
            ft[0]=s1; ft[1]=s2; ft[2]=s3;
            ft[3]=t00; ft[4]=t01; ft[5]=t02;
            ft[6]=t01; ft[7]=t11; ft[8]=t12;
            ft[9]=t02; ft[10]=t12; ft[11]=t22;
            ft[12]=dcl; ft[13]=logf(dcl);
            ft[14]=F00c; ft[15]=logf(F00c);
            #pragma unroll
            for (int a = 0; a < 9; a++)
                ft[16+a] = ok ? Cg[(size_t)i*9 + a] : 0.0f;
            #pragma unroll
            for (int a = 25; a < 32; a++) ft[a] = 0.0f;

            unsigned* wrow = reinterpret_cast<unsigned*>(fB + tid*40);
            #pragma unroll
            for (int c = 0; c < 16; c++){
                __half2 hv = __floats2half2_rn(ft[2*c], ft[2*c+1]);
                wrow[c] = *reinterpret_cast<unsigned*>(&hv);
            }
        }
        __syncthreads();                       // S1: features visible

        float acc[8][4];
        unsigned Ah[4][4];

        load_feat_frags1<2>(fB, mrow0, lane, Ah);

        // ---- MLP on HMMA (2-product: Ah*Bh + Ah*Bl) ----
        init_acc1<8>(acc, sb, lane);
        mma_block1<2,8>(acc, Ah, WF1H, WF1L, lane);
        act_frags1(acc, Ah);

        init_acc1<8>(acc, sb + 64, lane);
        mma_block1<4,8>(acc, Ah, WF2H, WF2L, lane);
        act_frags1(acc, Ah);

        init_acc1<8>(acc, sb + 128, lane);
        mma_block1<4,8>(acc, Ah, WF3H, WF3L, lane);
        act_frags1(acc, Ah);

        init_acc1<8>(acc, sb + 192, lane);
        mma_block1<4,8>(acc, Ah, WF4H, WF4L, lane);
        act_frags1(acc, Ah);

        init_acc1<2>(acc, sb + 256, lane);
        mma_block1<4,2>(acc, Ah, WF5H, WF5L, lane);

        __syncthreads();                       // S2: all fB reads done before overwrite

        // ---- scatter layer-5 D to staging (rows of own m-tile; aliases fB) ----
        {
            int g = lane >> 2, t2 = (lane & 3) * 2;
            int row = mrow0 + g;
            #pragma unroll
            for (int j = 0; j < 2; j++){
                int col = j*8 + t2;
                outS[row*20 + col]       = acc[j][0];
                outS[row*20 + col + 1]   = acc[j][1];
                outS[(row+8)*20 + col]   = acc[j][2];
                outS[(row+8)*20 + col+1] = acc[j][3];
            }
        }
        __syncthreads();                       // S3: outS visible

        if (ok){
            float o[9];
            #pragma unroll
            for (int c = 0; c < 9; c++) o[c] = outS[tid*20 + c];

            // ---- epilogue: sym, P = R*S, cauchy = P*F^T ----
            float s00 = o[0], s01 = 0.5f*(o[1]+o[3]), s02 = 0.5f*(o[2]+o[6]);
            float s11 = o[4], s12 = 0.5f*(o[5]+o[7]), s22 = o[8];

            float P00 = R0*s00 + R1*s01 + R2*s02;
            float P01 = R0*s01 + R1*s11 + R2*s12;
            float P02 = R0*s02 + R1*s12 + R2*s22;
            float P10 = R3*s00 + R4*s01 + R5*s02;
            float P11 = R3*s01 + R4*s11 + R5*s12;
            float P12 = R3*s02 + R4*s12 + R5*s22;
            float P20 = R6*s00 + R7*s01 + R8*s02;
            float P21 = R6*s01 + R7*s11 + R8*s12;
            float P22 = R6*s02 + R7*s12 + R8*s22;

            size_t o9 = (size_t)i*9;
            outg[o9+0] = P00*f[0] + P01*f[1] + P02*f[2];
            outg[o9+1] = P00*f[3] + P01*f[4] + P02*f[5];
            outg[o9+2] = P00*f[6] + P01*f[7] + P02*f[8];
            outg[o9+3] = P10*f[0] + P11*f[1] + P12*f[2];
            outg[o9+4] = P10*f[3] + P11*f[4] + P12*f[5];
            outg[o9+5] = P10*f[6] + P11*f[7] + P12*f[8];
            outg[o9+6] = P20*f[0] + P21*f[1] + P22*f[2];
            outg[o9+7] = P20*f[3] + P21*f[4] + P22*f[5];
            outg[o9+8] = P20*f[6] + P21*f[7] + P22*f[8];
        }
    }
}

// ---------------- launch ----------------
extern "C" void kernel_launch(void* const* d_in, const int* in_sizes, int n_in,
                              void* d_out, int out_size)
{
    const float* F   = (const float*)d_in[0];
    const float* C   = (const float*)d_in[1];
    const float* w1  = (const float*)d_in[2];
    const float* b1  = (const float*)d_in[3];
    const float* w2  = (const float*)d_in[4];
    const float* b2  = (const float*)d_in[5];
    const float* w3  = (const float*)d_in[6];
    const float* b3  = (const float*)d_in[7];
    const float* w4  = (const float*)d_in[8];
    const float* b4  = (const float*)d_in[9];
    const float* w5  = (const float*)d_in[10];
    const float* b5  = (const float*)d_in[11];
    const float* tlw = (const float*)d_in[12];
    const int*   tid = (const int*)d_in[13];
    float* out = (float*)d_out;

    int B = in_sizes[0] / 9;
    cudaFuncSetAttribute(stress_hmma_kernel,
                         cudaFuncAttributeMaxDynamicSharedMemorySize, SMEM_BYTES);

    int tiles = (B + TILE - 1) / TILE;
    int grid = tiles < 296 ? tiles : 296;   // 148 SMs x 2 CTAs

    stress_hmma_kernel<<<grid, NT, SMEM_BYTES>>>(
        F, C, w1, b1, w2, b2, w3, b3, w4, b4, w5, b5, tlw, tid, out, B);
}

// round 8
// speedup vs baseline: 3.6966x; 1.0284x over previous
#include <cuda_runtime.h>
#include <cuda_fp16.h>
#include <cstdint>

#define DI __device__ __forceinline__
typedef unsigned long long ull;

constexpr int NT   = 256;  // 8 warps; warp w owns m-tile rows [16w, 16w+16)
constexpr int TILE = 128;  // items per CTA-tile

// ---------------- smem layout (bytes) ----------------
constexpr int O_WF1H = 0;        // 8*2*32 uint2 = 4096 B
constexpr int O_WF1L = 4096;
constexpr int O_WF2H = 8192;     // 8*4*32 uint2 = 8192 B
constexpr int O_WF2L = 16384;
constexpr int O_WF3H = 24576;
constexpr int O_WF3L = 32768;
constexpr int O_WF4H = 40960;
constexpr int O_WF4L = 49152;
constexpr int O_WF5H = 57344;    // 2*4*32 uint2 = 2048 B
constexpr int O_WF5L = 59392;
constexpr int O_BIAS = 61440;    // 272 floats
constexpr int O_FEAT = 62528;    // 128 rows * 40 halves * 2B = 10240
constexpr int O_OUTS = 72768;    // 128 rows * 20 floats * 4B = 10240 (dedicated)
constexpr int SMEM_BYTES = 83008;

// ---------------- packed f32x2 helpers ----------------
DI ull pack2(float x, float y){
    ull v;
    asm("mov.b64 %0, {%1,%2};" : "=l"(v)
        : "r"(__float_as_uint(x)), "r"(__float_as_uint(y)));
    return v;
}
DI float2 unpack2(ull v){
    unsigned lo, hi;
    asm("mov.b64 {%0,%1}, %2;" : "=r"(lo), "=r"(hi) : "l"(v));
    return make_float2(__uint_as_float(lo), __uint_as_float(hi));
}
DI ull mul2(ull a, ull b){ ull d; asm("mul.rn.f32x2 %0,%1,%2;" : "=l"(d) : "l"(a), "l"(b)); return d; }
DI ull add2(ull a, ull b){ ull d; asm("add.rn.f32x2 %0,%1,%2;" : "=l"(d) : "l"(a), "l"(b)); return d; }
DI ull fma2(ull a, ull b, ull c){ ull d; asm("fma.rn.f32x2 %0,%1,%2,%3;" : "=l"(d) : "l"(a), "l"(b), "l"(c)); return d; }
DI float rcp_a(float x){ float r; asm("rcp.approx.f32 %0,%1;" : "=f"(r) : "f"(x)); return r; }
DI float ex2_a(float x){ float r; asm("ex2.approx.f32 %0,%1;" : "=f"(r) : "f"(x)); return r; }
DI ull dup2(float c){ unsigned u = __float_as_uint(c); return ((ull)u << 32) | u; }

// packed exact-GELU, restructured:
//   gelu(x) = 0.5(x+|x|) - 0.5|x|*pl(t)*e^{-x^2/2},  t = 1/(1 + p*c*|x|)
// (A&S 7.1.26 erf, |err| <= 1.5e-7; sign handling is algebraic, no select)
DI ull gelu2(ull x){
    const ull C_PC  = dup2(0.23164190f);      // 0.3275911 * sqrt(1/2)
    const ull C_ONE = dup2(1.0f);
    const ull C_A5  = dup2(1.061405429f);
    const ull C_A4  = dup2(-1.453152027f);
    const ull C_A3  = dup2(1.421413741f);
    const ull C_A2  = dup2(-0.284496736f);
    const ull C_A1  = dup2(0.254829592f);
    const ull C_ME  = dup2(-0.72134752044f);  // -log2(e)/2
    const ull C_H   = dup2(0.5f);
    const ull C_NH  = dup2(-0.5f);

    ull ax = x & 0x7FFFFFFF7FFFFFFFull;
    ull w  = fma2(ax, C_PC, C_ONE);
    float2 wf = unpack2(w);
    ull t  = pack2(rcp_a(wf.x), rcp_a(wf.y));
    ull pl = fma2(t, C_A5, C_A4);
    pl = fma2(t, pl, C_A3);
    pl = fma2(t, pl, C_A2);
    pl = fma2(t, pl, C_A1);
    pl = mul2(pl, t);
    ull x2 = mul2(x, x);
    ull mm = mul2(x2, C_ME);
    float2 mf = unpack2(mm);
    ull e  = pack2(ex2_a(mf.x), ex2_a(mf.y));
    ull pe = mul2(pl, e);
    pe = mul2(pe, ax);
    ull u = mul2(add2(x, ax), C_H);
    return fma2(pe, C_NH, u);
}

// packed f32 pair -> f16x2
DI unsigned cvt_h2(ull g){
    float2 gf = unpack2(g);
    unsigned h2;
    asm("cvt.rn.f16x2.f32 %0, %1, %2;" : "=r"(h2) : "f"(gf.y), "f"(gf.x));
    return h2;
}

DI void split2s(float v0, float v1, unsigned &hi, unsigned &lo){
    half h0 = __float2half_rn(v0), h1 = __float2half_rn(v1);
    half l0 = __float2half_rn(v0 - __half2float(h0));
    half l1 = __float2half_rn(v1 - __half2float(h1));
    hi = ((unsigned)__half_as_ushort(h1) << 16) | (unsigned)__half_as_ushort(h0);
    lo = ((unsigned)__half_as_ushort(l1) << 16) | (unsigned)__half_as_ushort(l0);
}

DI void mma16816(float (&c)[4], const unsigned (&a)[4], uint2 b){
    asm volatile(
        "mma.sync.aligned.m16n8k16.row.col.f32.f16.f16.f32 "
        "{%0,%1,%2,%3}, {%4,%5,%6,%7}, {%8,%9}, {%0,%1,%2,%3};"
        : "+f"(c[0]), "+f"(c[1]), "+f"(c[2]), "+f"(c[3])
        : "r"(a[0]), "r"(a[1]), "r"(a[2]), "r"(a[3]), "r"(b.x), "r"(b.y));
}

template<int NTI>
DI void init_acc1(float (&acc)[8][4], const float* bias, int lane){
    int t2 = (lane & 3) * 2;
    #pragma unroll
    for (int j = 0; j < NTI; j++){
        float2 b2v = *reinterpret_cast<const float2*>(bias + j*8 + t2);
        acc[j][0] = b2v.x; acc[j][1] = b2v.y;
        acc[j][2] = b2v.x; acc[j][3] = b2v.y;
    }
}

// one layer (single m-tile): Ah*Bh + Ah*Bl (weight hi/lo, activation hi only)
template<int KT, int NTI>
DI void mma_block1(float (&acc)[8][4],
                   const unsigned (&Ah)[4][4],
                   const uint2* __restrict__ wfh, const uint2* __restrict__ wfl,
                   int lane){
    #pragma unroll
    for (int kt = 0; kt < KT; kt++){
        #pragma unroll
        for (int j = 0; j < NTI; j++){
            uint2 bh = wfh[(j*KT + kt)*32 + lane];
            uint2 bl = wfl[(j*KT + kt)*32 + lane];
            mma16816(acc[j], Ah[kt], bh);
            mma16816(acc[j], Ah[kt], bl);
        }
    }
}

// D -> packed GELU -> next-layer A fragments (registers only)
DI void act_frags1(const float (&acc)[8][4], unsigned (&Ah)[4][4]){
    #pragma unroll
    for (int kk = 0; kk < 4; kk++)
    #pragma unroll
    for (int part = 0; part < 2; part++)
    #pragma unroll
    for (int pair = 0; pair < 2; pair++){
        int j = 2*kk + part;
        ull g = gelu2(pack2(acc[j][2*pair], acc[j][2*pair + 1]));
        Ah[kk][part*2 + pair] = cvt_h2(g);
    }
}

// A fragments for one 16-row m-tile from feature smem (row stride 40 halves)
template<int KT>
DI void load_feat_frags1(const half* __restrict__ fbase, int row0, int lane,
                         unsigned (&A)[4][4]){
    int g = lane >> 2, t2 = (lane & 3) * 2;
    int ra = row0 + g;
    #pragma unroll
    for (int kt = 0; kt < KT; kt++){
        const half* p0 = fbase + ra*40 + kt*16 + t2;
        const half* p1 = fbase + (ra + 8)*40 + kt*16 + t2;
        A[kt][0] = *reinterpret_cast<const unsigned*>(p0);
        A[kt][1] = *reinterpret_cast<const unsigned*>(p1);
        A[kt][2] = *reinterpret_cast<const unsigned*>(p0 + 8);
        A[kt][3] = *reinterpret_cast<const unsigned*>(p1 + 8);
    }
}

// stage weights into per-lane fragment order, fp16 hi/lo split
DI void stage(char* sm, int oh, int ol, const float* __restrict__ w,
              int Kreal, int Nreal, int ldw, int KT, int NTI, int tid){
    uint2* fh = reinterpret_cast<uint2*>(sm + oh);
    uint2* fl = reinterpret_cast<uint2*>(sm + ol);
    int total = NTI * KT * 32;
    for (int idx = tid; idx < total; idx += NT){
        int lane = idx & 31;
        int kt   = (idx >> 5) % KT;
        int nt   = idx / (32 * KT);
        int n  = nt*8 + (lane >> 2);
        int k0 = kt*16 + (lane & 3)*2;
        float v[4];
        #pragma unroll
        for (int q = 0; q < 4; q++){
            int k = k0 + (q >> 1)*8 + (q & 1);
            v[q] = (k < Kreal && n < Nreal) ? w[k*ldw + n] : 0.0f;
        }
        unsigned hx, lx, hy, ly;
        split2s(v[0], v[1], hx, lx);
        split2s(v[2], v[3], hy, ly);
        fh[idx] = make_uint2(hx, hy);
        fl[idx] = make_uint2(lx, ly);
    }
}

// ---------------- main fused kernel ----------------
__global__ void __launch_bounds__(NT, 2)
stress_hmma_kernel(const float* __restrict__ Fg, const float* __restrict__ Cg,
                   const float* __restrict__ w1, const float* __restrict__ b1,
                   const float* __restrict__ w2, const float* __restrict__ b2,
                   const float* __restrict__ w3, const float* __restrict__ b3,
                   const float* __restrict__ w4, const float* __restrict__ b4,
                   const float* __restrict__ w5, const float* __restrict__ b5,
                   const float* __restrict__ tlw, const int* __restrict__ traj_ids,
                   float* __restrict__ outg, int B)
{
    extern __shared__ __align__(16) char sm[];
    const int tid   = threadIdx.x;
    const int lane  = tid & 31;
    const int mrow0 = (tid >> 5) * 16;      // warp's m-tile base row
    const bool isPolar = (tid < TILE);      // warps 0-3: polar+epilogue; warps 4-7: features
    const int  item    = isPolar ? tid : (tid - TILE);

    // ---- stage weight fragments (once) ----
    stage(sm, O_WF1H, O_WF1L, w1, 25, 64, 64, 2, 8, tid);
    stage(sm, O_WF2H, O_WF2L, w2, 64, 64, 64, 4, 8, tid);
    stage(sm, O_WF3H, O_WF3L, w3, 64, 64, 64, 4, 8, tid);
    stage(sm, O_WF4H, O_WF4L, w4, 64, 64, 64, 4, 8, tid);
    stage(sm, O_WF5H, O_WF5L, w5, 64,  9,  9, 4, 2, tid);

    // ---- biases; fold constant latent into b1 ----
    float* sb = reinterpret_cast<float*>(sm + O_BIAS);
    if (tid < 64){
        int t = traj_ids[0];
        float a = b1[tid];
        #pragma unroll
        for (int e = 0; e < 32; e++)
            a = fmaf(tlw[t*32 + e], w1[(25+e)*64 + tid], a);
        sb[tid]       = a;
        sb[64  + tid] = b2[tid];
        sb[128 + tid] = b3[tid];
        sb[192 + tid] = b4[tid];
    }
    if (tid < 16) sb[256 + tid] = (tid < 9) ? b5[tid] : 0.0f;
    __syncthreads();

    half*  fB   = reinterpret_cast<half*>(sm + O_FEAT);   // 128 rows x 40 halves
    float* outS = reinterpret_cast<float*>(sm + O_OUTS);  // 128 rows x 20 floats

    const uint2* WF1H = (const uint2*)(sm + O_WF1H);
    const uint2* WF1L = (const uint2*)(sm + O_WF1L);
    const uint2* WF2H = (const uint2*)(sm + O_WF2H);
    const uint2* WF2L = (const uint2*)(sm + O_WF2L);
    const uint2* WF3H = (const uint2*)(sm + O_WF3H);
    const uint2* WF3L = (const uint2*)(sm + O_WF3L);
    const uint2* WF4H = (const uint2*)(sm + O_WF4H);
    const uint2* WF4L = (const uint2*)(sm + O_WF4L);
    const uint2* WF5H = (const uint2*)(sm + O_WF5H);
    const uint2* WF5L = (const uint2*)(sm + O_WF5L);

    for (int base = blockIdx.x * TILE; base < B; base += gridDim.x * TILE){
        const int  i  = base + item;
        const bool ok = (i < B);

        float f[9];
        float R0=1,R1=0,R2=0,R3=0,R4=1,R5=0,R6=0,R7=0,R8=1;

        // ---- load F (identity if OOB); both halves need it ----
        if (ok){
            #pragma unroll
            for (int a = 0; a < 9; a++) f[a] = Fg[(size_t)i*9 + a];
        } else {
            #pragma unroll
            for (int a = 0; a < 9; a++) f[a] = (a % 4 == 0) ? 1.0f : 0.0f;
        }

        if (isPolar){
            // ---- polar rotation: Newton X <- 0.5(X + X^-T), 6 iters ----
            R0=f[0];R1=f[1];R2=f[2];R3=f[3];R4=f[4];R5=f[5];R6=f[6];R7=f[7];R8=f[8];
            #pragma unroll 1
            for (int it = 0; it < 6; it++){
                float C00 = R4*R8 - R5*R7, C01 = R5*R6 - R3*R8, C02 = R3*R7 - R4*R6;
                float C10 = R2*R7 - R1*R8, C11 = R0*R8 - R2*R6, C12 = R1*R6 - R0*R7;
                float C20 = R1*R5 - R2*R4, C21 = R2*R3 - R0*R5, C22 = R0*R4 - R1*R3;
                float dR  = R0*C00 + R1*C01 + R2*C02;
                float hd  = 0.5f / dR;
                R0 = 0.5f*R0 + C00*hd; R1 = 0.5f*R1 + C01*hd; R2 = 0.5f*R2 + C02*hd;
                R3 = 0.5f*R3 + C10*hd; R4 = 0.5f*R4 + C11*hd; R5 = 0.5f*R5 + C12*hd;
                R6 = 0.5f*R6 + C20*hd; R7 = 0.5f*R7 + C21*hd; R8 = 0.5f*R8 + C22*hd;
            }
        } else {
            // ---- features for item = tid-128 ----
            float t00 = f[0]*f[0] + f[3]*f[3] + f[6]*f[6];
            float t01 = f[0]*f[1] + f[3]*f[4] + f[6]*f[7];
            float t02 = f[0]*f[2] + f[3]*f[5] + f[6]*f[8];
            float t11 = f[1]*f[1] + f[4]*f[4] + f[7]*f[7];
            float t12 = f[1]*f[2] + f[4]*f[5] + f[7]*f[8];
            float t22 = f[2]*f[2] + f[5]*f[5] + f[8]*f[8];

            float det = f[0]*(f[4]*f[8]-f[5]*f[7])
                      + f[1]*(f[5]*f[6]-f[3]*f[8])
                      + f[2]*(f[3]*f[7]-f[4]*f[6]);
            float dcl = (det < 0.0f) ? 1e-9f : det;

            float q  = (t00 + t11 + t22) * (1.0f/3.0f);
            float p1 = t01*t01 + t02*t02 + t12*t12;
            float m0 = t00 - q, m1 = t11 - q, m2 = t22 - q;
            float p2 = m0*m0 + m1*m1 + m2*m2 + 2.0f*p1;
            float p  = sqrtf(p2 * (1.0f/6.0f) + 1e-30f);
            float ip = 1.0f / p;
            float b00 = m0*ip, b11 = m1*ip, b22 = m2*ip;
            float c01 = t01*ip, c02 = t02*ip, c12 = t12*ip;
            float detB = b00*(b11*b22 - c12*c12)
                       - c01*(c01*b22 - c12*c02)
                       + c02*(c01*c12 - b11*c02);
            float r = fminf(1.0f, fmaxf(-1.0f, 0.5f*detB));
            float phi = acosf(r) * (1.0f/3.0f);
            float e1 = q + 2.0f*p*cosf(phi);
            float e3 = q + 2.0f*p*cosf(phi + 2.0943951023931953f);
            float e2 = 3.0f*q - e1 - e3;
            float s1 = sqrtf(fmaxf(e1, 0.0f));
            float s2 = sqrtf(fmaxf(e2, 0.0f));
            float s3 = sqrtf(fmaxf(e3, 0.0f));

            float F00c = fmaxf(f[0], 1e-6f);

            float ft[32];
            ft[0]=s1; ft[1]=s2; ft[2]=s3;
            ft[3]=t00; ft[4]=t01; ft[5]=t02;
            ft[6]=t01; ft[7]=t11; ft[8]=t12;
            ft[9]=t02; ft[10]=t12; ft[11]=t22;
            ft[12]=dcl; ft[13]=logf(dcl);
            ft[14]=F00c; ft[15]=logf(F00c);
            #pragma unroll
            for (int a = 0; a < 9; a++)
                ft[16+a] = ok ? Cg[(size_t)i*9 + a] : 0.0f;
            #pragma unroll
            for (int a = 25; a < 32; a++) ft[a] = 0.0f;

            unsigned* wrow = reinterpret_cast<unsigned*>(fB + item*40);
            #pragma unroll
            for (int c = 0; c < 16; c++){
                __half2 hv = __floats2half2_rn(ft[2*c], ft[2*c+1]);
                wrow[c] = *reinterpret_cast<unsigned*>(&hv);
            }
        }
        __syncthreads();                       // S1: features visible

        float acc[8][4];
        unsigned Ah[4][4];

        load_feat_frags1<2>(fB, mrow0, lane, Ah);

        // ---- MLP on HMMA (2-product: Ah*Bh + Ah*Bl) ----
        init_acc1<8>(acc, sb, lane);
        mma_block1<2,8>(acc, Ah, WF1H, WF1L, lane);
        act_frags1(acc, Ah);

        init_acc1<8>(acc, sb + 64, lane);
        mma_block1<4,8>(acc, Ah, WF2H, WF2L, lane);
        act_frags1(acc, Ah);

        init_acc1<8>(acc, sb + 128, lane);
        mma_block1<4,8>(acc, Ah, WF3H, WF3L, lane);
        act_frags1(acc, Ah);

        init_acc1<8>(acc, sb + 192, lane);
        mma_block1<4,8>(acc, Ah, WF4H, WF4L, lane);
        act_frags1(acc, Ah);

        init_acc1<2>(acc, sb + 256, lane);
        mma_block1<4,2>(acc, Ah, WF5H, WF5L, lane);

        // ---- scatter layer-5 D to dedicated staging ----
        {
            int g = lane >> 2, t2 = (lane & 3) * 2;
            int row = mrow0 + g;
            #pragma unroll
            for (int j = 0; j < 2; j++){
                int col = j*8 + t2;
                outS[row*20 + col]       = acc[j][0];
                outS[row*20 + col + 1]   = acc[j][1];
                outS[(row+8)*20 + col]   = acc[j][2];
                outS[(row+8)*20 + col+1] = acc[j][3];
            }
        }
        __syncthreads();                       // S2: outS visible

        if (isPolar && ok){
            float o[9];
            #pragma unroll
            for (int c = 0; c < 9; c++) o[c] = outS[item*20 + c];

            // ---- epilogue: sym, P = R*S, cauchy = P*F^T ----
            float s00 = o[0], s01 = 0.5f*(o[1]+o[3]), s02 = 0.5f*(o[2]+o[6]);
            float s11 = o[4], s12 = 0.5f*(o[5]+o[7]), s22 = o[8];

            float P00 = R0*s00 + R1*s01 + R2*s02;
            float P01 = R0*s01 + R1*s11 + R2*s12;
            float P02 = R0*s02 + R1*s12 + R2*s22;
            float P10 = R3*s00 + R4*s01 + R5*s02;
            float P11 = R3*s01 + R4*s11 + R5*s12;
            float P12 = R3*s02 + R4*s12 + R5*s22;
            float P20 = R6*s00 + R7*s01 + R8*s02;
            float P21 = R6*s01 + R7*s11 + R8*s12;
            float P22 = R6*s02 + R7*s12 + R8*s22;

            size_t o9 = (size_t)i*9;
            outg[o9+0] = P00*f[0] + P01*f[1] + P02*f[2];
            outg[o9+1] = P00*f[3] + P01*f[4] + P02*f[5];
            outg[o9+2] = P00*f[6] + P01*f[7] + P02*f[8];
            outg[o9+3] = P10*f[0] + P11*f[1] + P12*f[2];
            outg[o9+4] = P10*f[3] + P11*f[4] + P12*f[5];
            outg[o9+5] = P10*f[6] + P11*f[7] + P12*f[8];
            outg[o9+6] = P20*f[0] + P21*f[1] + P22*f[2];
            outg[o9+7] = P20*f[3] + P21*f[4] + P22*f[5];
            outg[o9+8] = P20*f[6] + P21*f[7] + P22*f[8];
        }
    }
}

// ---------------- launch ----------------
extern "C" void kernel_launch(void* const* d_in, const int* in_sizes, int n_in,
                              void* d_out, int out_size)
{
    const float* F   = (const float*)d_in[0];
    const float* C   = (const float*)d_in[1];
    const float* w1  = (const float*)d_in[2];
    const float* b1  = (const float*)d_in[3];
    const float* w2  = (const float*)d_in[4];
    const float* b2  = (const float*)d_in[5];
    const float* w3  = (const float*)d_in[6];
    const float* b3  = (const float*)d_in[7];
    const float* w4  = (const float*)d_in[8];
    const float* b4  = (const float*)d_in[9];
    const float* w5  = (const float*)d_in[10];
    const float* b5  = (const float*)d_in[11];
    const float* tlw = (const float*)d_in[12];
    const int*   tid = (const int*)d_in[13];
    float* out = (float*)d_out;

    int B = in_sizes[0] / 9;
    cudaFuncSetAttribute(stress_hmma_kernel,
                         cudaFuncAttributeMaxDynamicSharedMemorySize, SMEM_BYTES);

    int tiles = (B + TILE - 1) / TILE;
    int grid = tiles < 296 ? tiles : 296;   // 148 SMs x 2 CTAs

    stress_hmma_kernel<<<grid, NT, SMEM_BYTES>>>(
        F, C, w1, b1, w2, b2, w3, b3, w4, b4, w5, b5, tlw, tid, out, B);
}